// round 11
// baseline (speedup 1.0000x reference)
#include <cuda_runtime.h>
#include <cuda_bf16.h>

#define BB   64
#define DPT  128
#define HW   121
#define OCH  16
#define FEAT_SZ (OCH*HW)

typedef unsigned long long u64;
typedef unsigned int u32;
union F2U { u64 u; float2 f; };

__device__ __forceinline__ u64 fma2(u64 a, u64 b, u64 c) {
    u64 d; asm("fma.rn.f32x2 %0, %1, %2, %3;" : "=l"(d) : "l"(a), "l"(b), "l"(c)); return d;
}
__device__ __forceinline__ u64 dup2(float w) {
    u64 d; asm("mov.b64 %0, {%1, %1};" : "=l"(d) : "f"(w)); return d;
}
// mma.sync m16n8k16 bf16 (baseline PTX, compiles for compute_103)
__device__ __forceinline__ void mma_bf16(float (&c)[4], u32 a0, u32 a1, u32 a2, u32 a3,
                                         u32 b0, u32 b1) {
    asm volatile("mma.sync.aligned.m16n8k16.row.col.f32.bf16.bf16.f32 "
        "{%0,%1,%2,%3}, {%4,%5,%6,%7}, {%8,%9}, {%0,%1,%2,%3};"
        : "+f"(c[0]), "+f"(c[1]), "+f"(c[2]), "+f"(c[3])
        : "r"(a0), "r"(a1), "r"(a2), "r"(a3), "r"(b0), "r"(b1));
}
__device__ __forceinline__ u32 pack_bf16(__nv_bfloat16 lo, __nv_bfloat16 hi) {
    __nv_bfloat162 t = __nv_bfloat162(lo, hi);
    return *reinterpret_cast<u32*>(&t);
}

__device__ float g_sa1[BB*OCH*DPT*HW];
__device__ float g_sa2[BB*OCH*DPT*HW];
__device__ float g_feat[5*BB*OCH*HW];
__device__ float g_alpha[3*OCH*DPT];

__global__ void alpha_kernel(const float* __restrict__ cw, float* __restrict__ alpha)
{
    const int lo = blockIdx.x, tid = threadIdx.x;
    __shared__ float red[128];
    float wv = cw[lo*128 + tid];
    red[tid] = wv; __syncthreads();
    for (int s = 64; s > 0; s >>= 1) { if (tid < s) red[tid] = fmaxf(red[tid], red[tid+s]); __syncthreads(); }
    float mx = red[0]; __syncthreads();
    float e = expf(wv - mx);
    red[tid] = e; __syncthreads();
    for (int s = 64; s > 0; s >>= 1) { if (tid < s) red[tid] += red[tid+s]; __syncthreads(); }
    alpha[lo*128 + tid] = e / red[0];
}

// Layer-1 scalar conv (ICH=1), packed f32x2, fused cpr partials
__global__ void __launch_bounds__(256, 2) conv3d1_kernel(
    const float* __restrict__ in, const float* __restrict__ wt,
    const float* __restrict__ bias, float* __restrict__ out,
    const float* __restrict__ alpha, float* __restrict__ featL)
{
    const int d0 = blockIdx.x * 8;
    const int b  = blockIdx.y;
    extern __shared__ float sm[];
    float*  w_s = sm;                        // 63*16
    float2* in2 = (float2*)(sm + 63*16);     // 13*169
    __shared__ float alpha_s[128];
    const int tid = threadIdx.x;
    if (tid < 128) alpha_s[tid] = alpha[(tid >> 3)*128 + d0 + (tid & 7)];

    const int og = tid >> 7, pos = tid & 127;
    const int cpos = pos < HW ? pos : HW-1;
    const int h = cpos / 11, w = cpos - h*11;
    const int ppc = (h+1)*13 + (w+1);

    u64 acc[4][8];
    #pragma unroll
    for (int r = 0; r < 4; r++)
        #pragma unroll
        for (int o = 0; o < 8; o++) acc[r][o] = 0ULL;

    for (int t = tid; t < OCH*63; t += 256) { int o = t/63, r = t - o*63; w_s[r*16 + o] = wt[o*63 + r]; }
    for (int t = tid; t < 13*169; t += 256) {
        int dd = t/169, pp = t - dd*169;
        int h13 = pp/13, w13 = pp - h13*13, gd = d0 - 3 + dd;
        float v0 = 0.f, v1 = 0.f;
        if (h13 >= 1 && h13 <= 11 && w13 >= 1 && w13 <= 11) {
            const float* src = in + (size_t)b*DPT*HW + (h13-1)*11 + (w13-1);
            if (gd   >= 0 && gd   < DPT) v0 = src[(size_t)gd*HW];
            if (gd+1 >= 0 && gd+1 < DPT) v1 = src[(size_t)(gd+1)*HW];
        }
        in2[t] = make_float2(v0, v1);
    }
    __syncthreads();

    const u64*   col = (const u64*)in2 + ppc;
    const float* wb  = w_s + og*8;
    #pragma unroll 1
    for (int khw = 0; khw < 9; ++khw) {
        const int kh = khw/3, kw = khw - kh*3;
        const int off = (kh-1)*13 + (kw-1);
        u64 t[13];
        #pragma unroll
        for (int j = 0; j < 13; ++j) t[j] = col[j*169 + off];
        #pragma unroll
        for (int kd = 0; kd < 7; ++kd) {
            const float* wk = wb + (kd*9 + khw)*16;
            float4 wa = *reinterpret_cast<const float4*>(wk);
            float4 wc = *reinterpret_cast<const float4*>(wk + 4);
            u64 wd[8] = {dup2(wa.x), dup2(wa.y), dup2(wa.z), dup2(wa.w),
                         dup2(wc.x), dup2(wc.y), dup2(wc.z), dup2(wc.w)};
            #pragma unroll
            for (int r = 0; r < 4; ++r) {
                u64 a = t[kd + 2*r];
                #pragma unroll
                for (int o = 0; o < 8; ++o) acc[r][o] = fma2(a, wd[o], acc[r][o]);
            }
        }
    }

    if (pos < HW) {
        #pragma unroll
        for (int o = 0; o < 8; ++o) {
            const int oc = og*8 + o;
            const float bv = bias[oc];
            float* ob = out + ((size_t)(b*OCH + oc)*DPT + d0)*HW + pos;
            float fs = 0.f;
            #pragma unroll
            for (int r = 0; r < 4; ++r) {
                F2U a; a.u = acc[r][o];
                float v0 = fmaxf(a.f.x + bv, 0.f), v1 = fmaxf(a.f.y + bv, 0.f);
                ob[(2*r  )*HW] = v0;
                ob[(2*r+1)*HW] = v1;
                fs += alpha_s[oc*8 + 2*r]*v0 + alpha_s[oc*8 + 2*r + 1]*v1;
            }
            atomicAdd(&featL[b*FEAT_SZ + oc*HW + pos], fs);
        }
    }
}

// ---------------------------------------------------------------------------
// Layers 2/3: warp-level HMMA (mma.sync m16n8k16, bf16 2-split, 3 passes).
// CTA = one (p, b). D[o=16, d=128]: 1 m-tile x 16 n-tiles, K = ich per (j, kd).
// smem rows = 16 bf16 (32B data) padded to 48B -> 8-consecutive-row fragment
// loads hit all 32 banks (no swizzle). 8 warps x 2 n-tiles, full K per warp.
// ---------------------------------------------------------------------------
#define NDP   136
#define AROW  48
#define ASLAB (9*NDP*AROW)          // 58752 per split
#define WOFF  (2*ASLAB)             // 117504
#define WSPL  (9*7*16*AROW)         // 48384 per split
#define SMEM_TT (WOFF + 2*WSPL)     // 214272

template<bool WRITE_SA>
__global__ void __launch_bounds__(256, 1) convT_kernel(
    const float* __restrict__ in, const float* __restrict__ wt,
    const float* __restrict__ bias, float* __restrict__ out,
    const float* __restrict__ alpha, float* __restrict__ featL)
{
    extern __shared__ char smx[];
    const int p = blockIdx.x, b = blockIdx.y;
    const int h = p/11, w = p - h*11;
    const int tid = threadIdx.x, wid = tid >> 5, l = tid & 31;

    // stage activations: slab[s][j][dp][i], dp row = input depth dp-3
    for (int idx = tid; idx < 9*NDP*8; idx += 256) {
        int j  = idx / (NDP*8);
        int r  = idx - j*(NDP*8);
        int dp = r >> 3, i2 = r & 7;
        int gd = dp - 3;
        int hh = h + j/3 - 1, ww = w + (j%3) - 1;
        float x0 = 0.f, x1 = 0.f;
        if (gd >= 0 && gd < DPT && hh >= 0 && hh < 11 && ww >= 0 && ww < 11) {
            const float* src = in + ((size_t)(b*OCH)*DPT + gd)*HW + hh*11 + ww;
            x0 = src[(size_t)(i2*2  )*DPT*HW];
            x1 = src[(size_t)(i2*2+1)*DPT*HW];
        }
        __nv_bfloat16 h0 = __float2bfloat16(x0);
        __nv_bfloat16 h1 = __float2bfloat16(x1);
        __nv_bfloat16 r0 = __float2bfloat16(x0 - __bfloat162float(h0));
        __nv_bfloat16 r1 = __float2bfloat16(x1 - __bfloat162float(h1));
        char* dst = smx + j*(NDP*AROW) + dp*AROW + i2*4;
        *(u32*)dst           = pack_bf16(h0, h1);
        *(u32*)(dst + ASLAB) = pack_bf16(r0, r1);
    }
    // stage weights: W[s][j][kd][o][i]
    for (int idx = tid; idx < 9*7*16*8; idx += 256) {
        int j  = idx / 896;
        int r  = idx - j*896;
        int kd = r / 128;
        int q  = r - kd*128;
        int o  = q >> 3, i2 = q & 7;
        float x0 = wt[o*1008 + (i2*2  )*63 + kd*9 + j];
        float x1 = wt[o*1008 + (i2*2+1)*63 + kd*9 + j];
        __nv_bfloat16 h0 = __float2bfloat16(x0);
        __nv_bfloat16 h1 = __float2bfloat16(x1);
        __nv_bfloat16 r0 = __float2bfloat16(x0 - __bfloat162float(h0));
        __nv_bfloat16 r1 = __float2bfloat16(x1 - __bfloat162float(h1));
        char* dst = smx + WOFF + (j*7 + kd)*768 + o*AROW + i2*4;
        *(u32*)dst          = pack_bf16(h0, h1);
        *(u32*)(dst + WSPL) = pack_bf16(r0, r1);
    }
    __syncthreads();

    // fragment lane offsets
    const int t4    = (l & 3) * 4;
    const int row0  = l >> 2;                 // 0..7
    const int aoff0 = row0*AROW + t4;         // a0 (o = row0)
    const int aoff1 = (row0 + 8)*AROW + t4;   // a1 (o = row0+8)
    const int dln   = wid*16 + row0;          // B lane row base (nt=0)

    float c0[4] = {0.f,0.f,0.f,0.f};
    float c1[4] = {0.f,0.f,0.f,0.f};

    #pragma unroll 1
    for (int ps = 0; ps < 3; ++ps) {
        const char* Wp = smx + WOFF + (ps == 1 ? WSPL : 0);
        const char* Xp = smx + (ps == 2 ? ASLAB : 0);
        #pragma unroll 1
        for (int j = 0; j < 9; ++j) {
            const char* Wj = Wp + j*(7*768);
            const char* Xj = Xp + j*(NDP*AROW) + dln*AROW + t4;
            #pragma unroll
            for (int kd = 0; kd < 7; ++kd) {
                const char* Wk = Wj + kd*768;
                u32 a0 = *(const u32*)(Wk + aoff0);
                u32 a2 = *(const u32*)(Wk + aoff0 + 16);
                u32 a1 = *(const u32*)(Wk + aoff1);
                u32 a3 = *(const u32*)(Wk + aoff1 + 16);
                const char* Xk = Xj + kd*AROW;
                u32 b0 = *(const u32*)(Xk);
                u32 b1 = *(const u32*)(Xk + 16);
                u32 b2 = *(const u32*)(Xk + 8*AROW);
                u32 b3 = *(const u32*)(Xk + 8*AROW + 16);
                mma_bf16(c0, a0, a1, a2, a3, b0, b1);
                mma_bf16(c1, a0, a1, a2, a3, b2, b3);
            }
        }
    }

    __syncthreads();  // mma done everywhere; smem reusable

    // epilogue: bias+relu, sa store, fused cpr reduce
    const int o0 = row0, o1 = row0 + 8;
    const float bv0 = bias[o0], bv1 = bias[o1];
    float s0 = 0.f, s1 = 0.f;
    {
        float* cc[2] = {c0, c1};
        #pragma unroll
        for (int nt = 0; nt < 2; ++nt) {
            int d0 = wid*16 + nt*8 + (l & 3)*2;
            float v00 = fmaxf(cc[nt][0] + bv0, 0.f);
            float v01 = fmaxf(cc[nt][1] + bv0, 0.f);
            float v10 = fmaxf(cc[nt][2] + bv1, 0.f);
            float v11 = fmaxf(cc[nt][3] + bv1, 0.f);
            if (WRITE_SA) {
                out[((size_t)(b*OCH + o0)*DPT + d0  )*HW + p] = v00;
                out[((size_t)(b*OCH + o0)*DPT + d0+1)*HW + p] = v01;
                out[((size_t)(b*OCH + o1)*DPT + d0  )*HW + p] = v10;
                out[((size_t)(b*OCH + o1)*DPT + d0+1)*HW + p] = v11;
            }
            s0 += alpha[o0*128 + d0]*v00 + alpha[o0*128 + d0+1]*v01;
            s1 += alpha[o1*128 + d0]*v10 + alpha[o1*128 + d0+1]*v11;
        }
    }
    s0 += __shfl_xor_sync(0xFFFFFFFFu, s0, 1);
    s0 += __shfl_xor_sync(0xFFFFFFFFu, s0, 2);
    s1 += __shfl_xor_sync(0xFFFFFFFFu, s1, 1);
    s1 += __shfl_xor_sync(0xFFFFFFFFu, s1, 2);
    float* buf = (float*)smx;   // [o=16][warp=8]
    if ((l & 3) == 0) {
        buf[o0*8 + wid] = s0;
        buf[o1*8 + wid] = s1;
    }
    __syncthreads();
    if (tid < 16) {
        float s = 0.f;
        #pragma unroll
        for (int k = 0; k < 8; ++k) s += buf[tid*8 + k];
        featL[b*FEAT_SZ + tid*HW + p] = fmaxf(s, 0.f);
    }
}

__global__ void relu_kernel(float* x, int n)
{
    int t = blockIdx.x*blockDim.x + threadIdx.x;
    if (t < n) x[t] = fmaxf(x[t], 0.f);
}

__global__ void conv45_kernel(const float* __restrict__ feat2,
                              const float* __restrict__ w45, const float* __restrict__ b45,
                              float* __restrict__ feat3, float* __restrict__ feat4)
{
    const int b = blockIdx.x, tid = threadIdx.x;
    __shared__ float fa[FEAT_SZ], fb[FEAT_SZ];
    for (int t = tid; t < FEAT_SZ; t += 128) fa[t] = feat2[b*FEAT_SZ + t];
    __syncthreads();
    if (tid < HW) {
        int h = tid / 11, w = tid - h*11;
        for (int o = 0; o < 16; o++) {
            float acc = b45[o];
            for (int c = 0; c < 16; c++)
                for (int kh = 0; kh < 3; kh++) {
                    int hh = h + kh - 1; if (hh < 0 || hh >= 11) continue;
                    for (int kw = 0; kw < 3; kw++) {
                        int ww2 = w + kw - 1; if (ww2 < 0 || ww2 >= 11) continue;
                        acc += fa[c*HW + hh*11 + ww2] * w45[(o*16 + c)*9 + kh*3 + kw];
                    }
                }
            float v = fmaxf(acc, 0.f);
            fb[o*HW + tid] = v;
            feat3[b*FEAT_SZ + o*HW + tid] = v;
        }
    }
    __syncthreads();
    if (tid < HW) {
        int h = tid / 11, w = tid - h*11;
        for (int o = 0; o < 16; o++) {
            float acc = b45[16 + o];
            for (int c = 0; c < 16; c++)
                for (int kh = 0; kh < 3; kh++) {
                    int hh = h + kh - 1; if (hh < 0 || hh >= 11) continue;
                    for (int kw = 0; kw < 3; kw++) {
                        int ww2 = w + kw - 1; if (ww2 < 0 || ww2 >= 11) continue;
                        acc += fb[c*HW + hh*11 + ww2] * w45[2304 + (o*16 + c)*9 + kh*3 + kw];
                    }
                }
            feat4[b*FEAT_SZ + o*HW + tid] = fmaxf(acc, 0.f);
        }
    }
}

__global__ void side_kernel(const float* __restrict__ x, const float* __restrict__ feat,
    const float* __restrict__ sw,  const float* __restrict__ sb,
    const float* __restrict__ sow, const float* __restrict__ sob,
    const float* __restrict__ wa,  const float* __restrict__ ba,
    const float* __restrict__ wb,  const float* __restrict__ bbv,
    const float* __restrict__ ssw, const float* __restrict__ ssb,
    const float* __restrict__ fuse, float* __restrict__ out)
{
    const int i = blockIdx.x, b = blockIdx.y, tid = threadIdx.x;
    __shared__ float f_s[FEAT_SZ], act_s[HW], diff_s[HW], s_arr[128], xc[128], y1_s[144], y2_s[16];
    __shared__ int idx_s[5];

    for (int t = tid; t < FEAT_SZ; t += 128)
        f_s[t] = feat[i*(BB*FEAT_SZ) + b*FEAT_SZ + t];
    __syncthreads();

    if (tid < HW) {
        int h = tid / 11, w = tid - h*11;
        float acc = sb[i];
        for (int c = 0; c < 16; c++)
            for (int kh = 0; kh < 3; kh++) {
                int hh = h + kh - 1; if (hh < 0 || hh >= 11) continue;
                for (int kw = 0; kw < 3; kw++) {
                    int ww2 = w + kw - 1; if (ww2 < 0 || ww2 >= 11) continue;
                    acc += f_s[c*HW + hh*11 + ww2] * sw[(i*16 + c)*9 + kh*3 + kw];
                }
            }
        act_s[tid] = acc;
    }
    __syncthreads();
    if (tid < HW) diff_s[tid] = fabsf(act_s[tid] - act_s[60]);
    __syncthreads();
    if (tid == 0) {
        for (int j = 0; j < 5; j++) {
            float best = 3.4e38f; int bi = 0;
            for (int p = 0; p < HW; p++) { float d = diff_s[p]; if (d < best) { best = d; bi = p; } }
            idx_s[j] = bi; diff_s[bi] = 3.4e38f;
        }
    }
    __syncthreads();
    {
        float s = 0.f;
        const float* xb = x + (size_t)(b*128 + tid)*HW;
        #pragma unroll
        for (int j = 0; j < 5; j++) s += xb[idx_s[j]];
        s_arr[tid] = s;
        xc[tid] = xb[60];
    }
    __syncthreads();
    for (int t = tid; t < 144; t += 128) {
        int o = t / 9, j = t - o*9;
        int pj = 62 + 2*(j/3), qj = 62 + 2*(j%3);
        float acc = ba[i*16 + o];
        #pragma unroll
        for (int ch = 0; ch < 2; ch++) {
            const float* num = ch ? xc : s_arr;
            #pragma unroll
            for (int eh = 0; eh < 3; eh++)
                #pragma unroll
                for (int ew = 0; ew < 3; ew++) {
                    int r = pj + eh - 1, c = qj + ew - 1;
                    float den = num[c];
                    den = fabsf(den) < 0.01f ? 0.01f : den;
                    acc += (num[r] / den) * wa[(((i*16 + o)*2 + ch)*3 + eh)*3 + ew];
                }
        }
        y1_s[o*9 + j] = fmaxf(acc, 0.f);
    }
    __syncthreads();
    if (tid < 16) {
        float acc = bbv[i*16 + tid];
        for (int c = 0; c < 16; c++)
            #pragma unroll
            for (int j = 0; j < 9; j++)
                acc += y1_s[c*9 + j] * wb[((i*16 + tid)*16 + c)*9 + j];
        y2_s[tid] = fmaxf(acc, 0.f);
    }
    __syncthreads();
    if (tid < 16) {
        float sa_v = sob[i*16 + tid];
        for (int k = 0; k < 16; k++) sa_v += f_s[k*HW + 60] * sow[(i*16 + tid)*16 + k];
        float sp_v = ssb[i*16 + tid];
        for (int c = 0; c < 16; c++) sp_v += y2_s[c] * ssw[(i*16 + tid)*16 + c];
        atomicAdd(&out[b*16 + tid], fuse[i]*sa_v + fuse[5 + i]*sp_v);
    }
}

__global__ void zero_kernel(float* out, int n)
{
    int t = blockIdx.x*blockDim.x + threadIdx.x;
    if (t < n) out[t] = 0.f;
}

extern "C" void kernel_launch(void* const* d_in, const int* in_sizes, int n_in,
                              void* d_out, int out_size)
{
    const float* x      = (const float*)d_in[0];
    const float* w3d1   = (const float*)d_in[1];
    const float* b3d1   = (const float*)d_in[2];
    const float* w3d23  = (const float*)d_in[3];
    const float* b3d23  = (const float*)d_in[4];
    const float* cpr_w  = (const float*)d_in[5];
    const float* w2d45  = (const float*)d_in[6];
    const float* b2d45  = (const float*)d_in[7];
    const float* seg_w  = (const float*)d_in[8];
    const float* seg_b  = (const float*)d_in[9];
    const float* so_w   = (const float*)d_in[10];
    const float* so_b   = (const float*)d_in[11];
    const float* sp_wa  = (const float*)d_in[12];
    const float* sp_ba  = (const float*)d_in[13];
    const float* sp_wb  = (const float*)d_in[14];
    const float* sp_bb  = (const float*)d_in[15];
    const float* sp_sw  = (const float*)d_in[16];
    const float* sp_sb  = (const float*)d_in[17];
    const float* fuse   = (const float*)d_in[18];
    float* out = (float*)d_out;

    float *sa1, *sa2, *feat, *alpha;
    cudaGetSymbolAddress((void**)&sa1,   g_sa1);
    cudaGetSymbolAddress((void**)&sa2,   g_sa2);
    cudaGetSymbolAddress((void**)&feat,  g_feat);
    cudaGetSymbolAddress((void**)&alpha, g_alpha);

    const int SMEM1 = 63*16*4 + 13*169*8;
    cudaFuncSetAttribute((const void*)conv3d1_kernel, cudaFuncAttributeMaxDynamicSharedMemorySize, SMEM1);
    cudaFuncSetAttribute((const void*)convT_kernel<true>,  cudaFuncAttributeMaxDynamicSharedMemorySize, SMEM_TT);
    cudaFuncSetAttribute((const void*)convT_kernel<false>, cudaFuncAttributeMaxDynamicSharedMemorySize, SMEM_TT);

    alpha_kernel<<<48, 128>>>(cpr_w, alpha);
    zero_kernel<<<(out_size + 255)/256, 256>>>(out, out_size);
    zero_kernel<<<(BB*FEAT_SZ + 255)/256, 256>>>(feat, BB*FEAT_SZ);

    conv3d1_kernel<<<dim3(16, BB), 256, SMEM1>>>(
        x, w3d1, b3d1, sa1, alpha + 0*2048, feat + 0*(BB*FEAT_SZ));
    relu_kernel<<<(BB*FEAT_SZ + 255)/256, 256>>>(feat, BB*FEAT_SZ);

    convT_kernel<true><<<dim3(HW, BB), 256, SMEM_TT>>>(
        sa1, w3d23, b3d23, sa2, alpha + 1*2048, feat + 1*(BB*FEAT_SZ));

    convT_kernel<false><<<dim3(HW, BB), 256, SMEM_TT>>>(
        sa2, w3d23 + 16128, b3d23 + 16, sa1 /*unused*/, alpha + 2*2048, feat + 2*(BB*FEAT_SZ));

    conv45_kernel<<<BB, 128>>>(feat + 2*(BB*FEAT_SZ), w2d45, b2d45,
                               feat + 3*(BB*FEAT_SZ), feat + 4*(BB*FEAT_SZ));

    side_kernel<<<dim3(5, BB), 128>>>(x, feat, seg_w, seg_b, so_w, so_b,
                                      sp_wa, sp_ba, sp_wb, sp_bb, sp_sw, sp_sb,
                                      fuse, out);
}

// round 12
// speedup vs baseline: 2.5025x; 2.5025x over previous
#include <cuda_runtime.h>
#include <cuda_bf16.h>

#define BB   64
#define DPT  128
#define HW   121
#define OCH  16
#define FEAT_SZ (OCH*HW)

typedef unsigned long long u64;

union F2U { u64 u; float2 f; };

__device__ __forceinline__ u64 fma2(u64 a, u64 b, u64 c) {
    u64 d; asm("fma.rn.f32x2 %0, %1, %2, %3;" : "=l"(d) : "l"(a), "l"(b), "l"(c)); return d;
}
__device__ __forceinline__ u64 dup2(float w) {
    u64 d; asm("mov.b64 %0, {%1, %1};" : "=l"(d) : "f"(w)); return d;
}

// Scratch (device globals)
__device__ float g_sa1[BB*OCH*DPT*HW];
__device__ float g_sa2[BB*OCH*DPT*HW];
__device__ float g_feat[5*BB*OCH*HW];
__device__ float g_alpha[3*OCH*DPT];

// ---------------------------------------------------------------------------
// alpha = softmax over d of cpr_w[l][o][:]
// ---------------------------------------------------------------------------
__global__ void alpha_kernel(const float* __restrict__ cw, float* __restrict__ alpha)
{
    const int lo = blockIdx.x, tid = threadIdx.x;
    __shared__ float red[128];
    float wv = cw[lo*128 + tid];
    red[tid] = wv; __syncthreads();
    for (int s = 64; s > 0; s >>= 1) { if (tid < s) red[tid] = fmaxf(red[tid], red[tid+s]); __syncthreads(); }
    float mx = red[0]; __syncthreads();
    float e = expf(wv - mx);
    red[tid] = e; __syncthreads();
    for (int s = 64; s > 0; s >>= 1) { if (tid < s) red[tid] += red[tid+s]; __syncthreads(); }
    alpha[lo*128 + tid] = e / red[0];
}

// ---------------------------------------------------------------------------
// 3D conv (R4 body: ii -> kd (unroll 1) -> khw (unrolled 9); depth-pair f32x2;
// smem weights non-duplicated, uniform LDS.128, dup2 on ALU pipe), with the
// R8 fused-cpr epilogue: relu(+bias), optional sa store, atomicAdd of
// sum_d alpha[o][d]*relu(v) into feat[b,o,pos]. Outer relu applied later.
// ---------------------------------------------------------------------------
template<int ICH, int CHK, bool WRITE_SA>
__global__ void __launch_bounds__(256, 2) conv3d9_kernel(
    const float* __restrict__ in, const float* __restrict__ wt,
    const float* __restrict__ bias, float* __restrict__ out,
    const float* __restrict__ alpha, float* __restrict__ featL)
{
    const int d0 = blockIdx.x * 8;
    const int b  = blockIdx.y;
    extern __shared__ float sm[];
    float*  w_s = sm;                               // CHK*63*16 floats
    float2* in2 = (float2*)(sm + CHK*63*16);        // CHK*13*169 float2 (depth pairs)
    __shared__ float alpha_s[128];
    const int tid = threadIdx.x;

    if (tid < 128) alpha_s[tid] = alpha[(tid >> 3)*128 + d0 + (tid & 7)];

    const int og  = tid >> 7;
    const int pos = tid & 127;
    const int cpos = pos < HW ? pos : HW-1;       // clamp dead lanes
    const int h = cpos / 11, w = cpos - h*11;
    const int ppc = (h+1)*13 + (w+1);

    u64 acc[4][8];   // [depth-pair][out-channel]
    #pragma unroll
    for (int r = 0; r < 4; r++)
        #pragma unroll
        for (int o = 0; o < 8; o++) acc[r][o] = 0ULL;

    for (int c0 = 0; c0 < ICH; c0 += CHK) {
        __syncthreads();
        // stage weights: wt[o][(c0+ii)*63 + r] -> w_s[(ii*63+r)*16 + o]
        for (int t = tid; t < OCH*CHK*63; t += 256) {
            int o = t / (CHK*63);
            int r = t - o*(CHK*63);
            w_s[r*16 + o] = wt[o*(ICH*63) + c0*63 + r];
        }
        // stage input depth-pairs: rows dd=0..12, (in[gd], in[gd+1]), gd=d0-3+dd
        for (int t = tid; t < CHK*13*169; t += 256) {
            int ii  = t / (13*169);
            int rem = t - ii*(13*169);
            int dd  = rem / 169;
            int pp  = rem - dd*169;
            int h13 = pp / 13, w13 = pp - h13*13;
            int gd  = d0 - 3 + dd;
            float v0 = 0.f, v1 = 0.f;
            if (h13 >= 1 && h13 <= 11 && w13 >= 1 && w13 <= 11) {
                const float* src = in + ((size_t)(b*ICH + c0 + ii)*DPT)*HW + (h13-1)*11 + (w13-1);
                if (gd   >= 0 && gd   < DPT) v0 = src[(size_t)gd*HW];
                if (gd+1 >= 0 && gd+1 < DPT) v1 = src[(size_t)(gd+1)*HW];
            }
            in2[t] = make_float2(v0, v1);
        }
        __syncthreads();

        for (int ii = 0; ii < CHK; ++ii) {
            #pragma unroll 1
            for (int kd = 0; kd < 7; ++kd) {
                const u64*   ib = (const u64*)in2 + (ii*13 + kd)*169 + ppc;
                const float* wb = w_s + ((ii*63 + kd*9))*16 + og*8;
                #pragma unroll
                for (int khw = 0; khw < 9; ++khw) {
                    const int kh = khw / 3, kw = khw - kh*3;
                    const int off = (kh - 1)*13 + (kw - 1);
                    float4 wa = *reinterpret_cast<const float4*>(wb + khw*16);
                    float4 wc = *reinterpret_cast<const float4*>(wb + khw*16 + 4);
                    u64 wd[8];
                    wd[0] = dup2(wa.x); wd[1] = dup2(wa.y);
                    wd[2] = dup2(wa.z); wd[3] = dup2(wa.w);
                    wd[4] = dup2(wc.x); wd[5] = dup2(wc.y);
                    wd[6] = dup2(wc.z); wd[7] = dup2(wc.w);
                    #pragma unroll
                    for (int r = 0; r < 4; ++r) {
                        u64 a = ib[(2*r)*169 + off];
                        #pragma unroll
                        for (int o = 0; o < 8; ++o)
                            acc[r][o] = fma2(a, wd[o], acc[r][o]);
                    }
                }
            }
        }
    }
    __syncthreads();   // alpha_s visible

    if (pos < HW) {
        #pragma unroll
        for (int o = 0; o < 8; ++o) {
            const int oc = og*8 + o;
            const float bv = bias[oc];
            float* ob = out + ((size_t)(b*OCH + oc)*DPT + d0)*HW + pos;
            float fs = 0.f;
            #pragma unroll
            for (int r = 0; r < 4; ++r) {
                F2U a; a.u = acc[r][o];
                float v0 = fmaxf(a.f.x + bv, 0.f);
                float v1 = fmaxf(a.f.y + bv, 0.f);
                if (WRITE_SA) {
                    ob[(2*r  )*HW] = v0;
                    ob[(2*r+1)*HW] = v1;
                }
                fs += alpha_s[oc*8 + 2*r]*v0 + alpha_s[oc*8 + 2*r + 1]*v1;
            }
            atomicAdd(&featL[b*FEAT_SZ + oc*HW + pos], fs);
        }
    }
}

// ---------------------------------------------------------------------------
__global__ void relu_kernel(float* x, int n)
{
    int t = blockIdx.x*blockDim.x + threadIdx.x;
    if (t < n) x[t] = fmaxf(x[t], 0.f);
}

// ---------------------------------------------------------------------------
// conv4/conv5 2D: relu(conv2d(3x3,pad1)) twice. One block per batch.
// ---------------------------------------------------------------------------
__global__ void conv45_kernel(const float* __restrict__ feat2,
                              const float* __restrict__ w45, const float* __restrict__ b45,
                              float* __restrict__ feat3, float* __restrict__ feat4)
{
    const int b = blockIdx.x, tid = threadIdx.x;
    __shared__ float fa[FEAT_SZ], fb[FEAT_SZ];
    for (int t = tid; t < FEAT_SZ; t += 128) fa[t] = feat2[b*FEAT_SZ + t];
    __syncthreads();
    if (tid < HW) {
        int h = tid / 11, w = tid - h*11;
        for (int o = 0; o < 16; o++) {
            float acc = b45[o];
            for (int c = 0; c < 16; c++)
                #pragma unroll
                for (int kh = 0; kh < 3; kh++) {
                    int hh = h + kh - 1; if (hh < 0 || hh >= 11) continue;
                    #pragma unroll
                    for (int kw = 0; kw < 3; kw++) {
                        int ww2 = w + kw - 1; if (ww2 < 0 || ww2 >= 11) continue;
                        acc += fa[c*HW + hh*11 + ww2] * w45[(o*16 + c)*9 + kh*3 + kw];
                    }
                }
            float v = fmaxf(acc, 0.f);
            fb[o*HW + tid] = v;
            feat3[b*FEAT_SZ + o*HW + tid] = v;
        }
    }
    __syncthreads();
    if (tid < HW) {
        int h = tid / 11, w = tid - h*11;
        for (int o = 0; o < 16; o++) {
            float acc = b45[16 + o];
            for (int c = 0; c < 16; c++)
                #pragma unroll
                for (int kh = 0; kh < 3; kh++) {
                    int hh = h + kh - 1; if (hh < 0 || hh >= 11) continue;
                    #pragma unroll
                    for (int kw = 0; kw < 3; kw++) {
                        int ww2 = w + kw - 1; if (ww2 < 0 || ww2 >= 11) continue;
                        acc += fb[c*HW + hh*11 + ww2] * w45[2304 + (o*16 + c)*9 + kh*3 + kw];
                    }
                }
            feat4[b*FEAT_SZ + o*HW + tid] = fmaxf(acc, 0.f);
        }
    }
}

// ---------------------------------------------------------------------------
// Side head: per (side i, batch b).
// ---------------------------------------------------------------------------
__global__ void side_kernel(const float* __restrict__ x, const float* __restrict__ feat,
    const float* __restrict__ sw,  const float* __restrict__ sb,
    const float* __restrict__ sow, const float* __restrict__ sob,
    const float* __restrict__ wa,  const float* __restrict__ ba,
    const float* __restrict__ wb,  const float* __restrict__ bbv,
    const float* __restrict__ ssw, const float* __restrict__ ssb,
    const float* __restrict__ fuse, float* __restrict__ out)
{
    const int i = blockIdx.x, b = blockIdx.y, tid = threadIdx.x;
    __shared__ float f_s[FEAT_SZ], act_s[HW], diff_s[HW], s_arr[128], xc[128], y1_s[144], y2_s[16];
    __shared__ int idx_s[5];

    for (int t = tid; t < FEAT_SZ; t += 128)
        f_s[t] = feat[i*(BB*FEAT_SZ) + b*FEAT_SZ + t];
    __syncthreads();

    if (tid < HW) {
        int h = tid / 11, w = tid - h*11;
        float acc = sb[i];
        for (int c = 0; c < 16; c++)
            #pragma unroll
            for (int kh = 0; kh < 3; kh++) {
                int hh = h + kh - 1; if (hh < 0 || hh >= 11) continue;
                #pragma unroll
                for (int kw = 0; kw < 3; kw++) {
                    int ww2 = w + kw - 1; if (ww2 < 0 || ww2 >= 11) continue;
                    acc += f_s[c*HW + hh*11 + ww2] * sw[(i*16 + c)*9 + kh*3 + kw];
                }
            }
        act_s[tid] = acc;
    }
    __syncthreads();
    if (tid < HW) diff_s[tid] = fabsf(act_s[tid] - act_s[60]);
    __syncthreads();
    if (tid == 0) {
        for (int j = 0; j < 5; j++) {
            float best = 3.4e38f; int bi = 0;
            for (int p = 0; p < HW; p++) { float d = diff_s[p]; if (d < best) { best = d; bi = p; } }
            idx_s[j] = bi; diff_s[bi] = 3.4e38f;
        }
    }
    __syncthreads();
    {
        float s = 0.f;
        const float* xb = x + (size_t)(b*128 + tid)*HW;
        #pragma unroll
        for (int j = 0; j < 5; j++) s += xb[idx_s[j]];
        s_arr[tid] = s;
        xc[tid] = xb[60];
    }
    __syncthreads();
    for (int t = tid; t < 144; t += 128) {
        int o = t / 9, j = t - o*9;
        int pj = 62 + 2*(j/3), qj = 62 + 2*(j%3);
        float acc = ba[i*16 + o];
        #pragma unroll
        for (int ch = 0; ch < 2; ch++) {
            const float* num = ch ? xc : s_arr;
            #pragma unroll
            for (int eh = 0; eh < 3; eh++)
                #pragma unroll
                for (int ew = 0; ew < 3; ew++) {
                    int r = pj + eh - 1, c = qj + ew - 1;
                    float den = num[c];
                    den = fabsf(den) < 0.01f ? 0.01f : den;
                    acc += (num[r] / den) * wa[(((i*16 + o)*2 + ch)*3 + eh)*3 + ew];
                }
        }
        y1_s[o*9 + j] = fmaxf(acc, 0.f);
    }
    __syncthreads();
    if (tid < 16) {
        float acc = bbv[i*16 + tid];
        for (int c = 0; c < 16; c++)
            #pragma unroll
            for (int j = 0; j < 9; j++)
                acc += y1_s[c*9 + j] * wb[((i*16 + tid)*16 + c)*9 + j];
        y2_s[tid] = fmaxf(acc, 0.f);
    }
    __syncthreads();
    if (tid < 16) {
        float sa_v = sob[i*16 + tid];
        for (int k = 0; k < 16; k++) sa_v += f_s[k*HW + 60] * sow[(i*16 + tid)*16 + k];
        float sp_v = ssb[i*16 + tid];
        for (int c = 0; c < 16; c++) sp_v += y2_s[c] * ssw[(i*16 + tid)*16 + c];
        atomicAdd(&out[b*16 + tid], fuse[i]*sa_v + fuse[5 + i]*sp_v);
    }
}

__global__ void zero_kernel(float* out, int n)
{
    int t = blockIdx.x*blockDim.x + threadIdx.x;
    if (t < n) out[t] = 0.f;
}

// ---------------------------------------------------------------------------
extern "C" void kernel_launch(void* const* d_in, const int* in_sizes, int n_in,
                              void* d_out, int out_size)
{
    const float* x      = (const float*)d_in[0];
    const float* w3d1   = (const float*)d_in[1];
    const float* b3d1   = (const float*)d_in[2];
    const float* w3d23  = (const float*)d_in[3];
    const float* b3d23  = (const float*)d_in[4];
    const float* cpr_w  = (const float*)d_in[5];
    const float* w2d45  = (const float*)d_in[6];
    const float* b2d45  = (const float*)d_in[7];
    const float* seg_w  = (const float*)d_in[8];
    const float* seg_b  = (const float*)d_in[9];
    const float* so_w   = (const float*)d_in[10];
    const float* so_b   = (const float*)d_in[11];
    const float* sp_wa  = (const float*)d_in[12];
    const float* sp_ba  = (const float*)d_in[13];
    const float* sp_wb  = (const float*)d_in[14];
    const float* sp_bb  = (const float*)d_in[15];
    const float* sp_sw  = (const float*)d_in[16];
    const float* sp_sb  = (const float*)d_in[17];
    const float* fuse   = (const float*)d_in[18];
    float* out = (float*)d_out;

    float *sa1, *sa2, *feat, *alpha;
    cudaGetSymbolAddress((void**)&sa1,   g_sa1);
    cudaGetSymbolAddress((void**)&sa2,   g_sa2);
    cudaGetSymbolAddress((void**)&feat,  g_feat);
    cudaGetSymbolAddress((void**)&alpha, g_alpha);

    const int SMEM16 = 4*63*16*4 + 4*13*169*8;   // 86,432 B (2 blocks/SM)
    const int SMEM1  = 1*63*16*4 + 1*13*169*8;   // 21,608 B
    cudaFuncSetAttribute((const void*)conv3d9_kernel<16,4,true>,  cudaFuncAttributeMaxDynamicSharedMemorySize, SMEM16);
    cudaFuncSetAttribute((const void*)conv3d9_kernel<16,4,false>, cudaFuncAttributeMaxDynamicSharedMemorySize, SMEM16);
    cudaFuncSetAttribute((const void*)conv3d9_kernel<1,1,true>,   cudaFuncAttributeMaxDynamicSharedMemorySize, SMEM1);

    alpha_kernel<<<48, 128>>>(cpr_w, alpha);
    zero_kernel<<<(out_size + 255)/256, 256>>>(out, out_size);
    zero_kernel<<<(3*BB*FEAT_SZ + 255)/256, 256>>>(feat, 3*BB*FEAT_SZ);

    conv3d9_kernel<1,1,true><<<dim3(16, BB), 256, SMEM1>>>(
        x, w3d1, b3d1, sa1, alpha + 0*2048, feat + 0*(BB*FEAT_SZ));

    conv3d9_kernel<16,4,true><<<dim3(16, BB), 256, SMEM16>>>(
        sa1, w3d23, b3d23, sa2, alpha + 1*2048, feat + 1*(BB*FEAT_SZ));

    conv3d9_kernel<16,4,false><<<dim3(16, BB), 256, SMEM16>>>(
        sa2, w3d23 + 16128, b3d23 + 16, sa1 /*unused*/, alpha + 2*2048, feat + 2*(BB*FEAT_SZ));

    relu_kernel<<<(3*BB*FEAT_SZ + 255)/256, 256>>>(feat, 3*BB*FEAT_SZ);

    conv45_kernel<<<BB, 128>>>(feat + 2*(BB*FEAT_SZ), w2d45, b2d45,
                               feat + 3*(BB*FEAT_SZ), feat + 4*(BB*FEAT_SZ));

    side_kernel<<<dim3(5, BB), 128>>>(x, feat, seg_w, seg_b, so_w, so_b,
                                      sp_wa, sp_ba, sp_wb, sp_bb, sp_sw, sp_sb,
                                      fuse, out);
}

// round 13
// speedup vs baseline: 2.5294x; 1.0108x over previous
#include <cuda_runtime.h>
#include <cuda_bf16.h>

#define BB   64
#define DPT  128
#define HW   121
#define OCH  16
#define FEAT_SZ (OCH*HW)

typedef unsigned long long u64;
typedef unsigned int u32;
union F2U { u64 u; float2 f; };

__device__ __forceinline__ u64 fma2(u64 a, u64 b, u64 c) {
    u64 d; asm("fma.rn.f32x2 %0, %1, %2, %3;" : "=l"(d) : "l"(a), "l"(b), "l"(c)); return d;
}
__device__ __forceinline__ u64 dup2(float w) {
    u64 d; asm("mov.b64 %0, {%1, %1};" : "=l"(d) : "f"(w)); return d;
}
__device__ __forceinline__ void mma_bf16(float (&c)[4], u32 a0, u32 a1, u32 a2, u32 a3,
                                         u32 b0, u32 b1) {
    asm volatile("mma.sync.aligned.m16n8k16.row.col.f32.bf16.bf16.f32 "
        "{%0,%1,%2,%3}, {%4,%5,%6,%7}, {%8,%9}, {%0,%1,%2,%3};"
        : "+f"(c[0]), "+f"(c[1]), "+f"(c[2]), "+f"(c[3])
        : "r"(a0), "r"(a1), "r"(a2), "r"(a3), "r"(b0), "r"(b1));
}
__device__ __forceinline__ u32 pack_bf16(__nv_bfloat16 lo, __nv_bfloat16 hi) {
    __nv_bfloat162 t = __nv_bfloat162(lo, hi);
    return *reinterpret_cast<u32*>(&t);
}

__device__ float g_sa1[BB*OCH*DPT*HW];
__device__ float g_sa2[BB*OCH*DPT*HW];
__device__ float g_feat[5*BB*OCH*HW];
__device__ float g_alpha[3*OCH*DPT];
__device__ u32   g_wsplit[2*16128];   // per layer: [s2][kk63][o16][ip8] u32 bf16-pairs

// ---------------------------------------------------------------------------
__global__ void alpha_kernel(const float* __restrict__ cw, float* __restrict__ alpha)
{
    const int lo = blockIdx.x, tid = threadIdx.x;
    __shared__ float red[128];
    float wv = cw[lo*128 + tid];
    red[tid] = wv; __syncthreads();
    for (int s = 64; s > 0; s >>= 1) { if (tid < s) red[tid] = fmaxf(red[tid], red[tid+s]); __syncthreads(); }
    float mx = red[0]; __syncthreads();
    float e = expf(wv - mx);
    red[tid] = e; __syncthreads();
    for (int s = 64; s > 0; s >>= 1) { if (tid < s) red[tid] += red[tid+s]; __syncthreads(); }
    alpha[lo*128 + tid] = e / red[0];
}

// pre-split one conv layer's weights into bf16 hi/lo pairs, coalesced layout
__global__ void wsplit_kernel(const float* __restrict__ wt, u32* __restrict__ dst)
{
    int t = blockIdx.x*256 + threadIdx.x;
    if (t < 8064) {
        int kk = t >> 7;              // /128
        int r  = t & 127;
        int o  = r >> 3, ip = r & 7;
        float x0 = wt[o*1008 + (2*ip  )*63 + kk];
        float x1 = wt[o*1008 + (2*ip+1)*63 + kk];
        __nv_bfloat16 h0 = __float2bfloat16(x0);
        __nv_bfloat16 h1 = __float2bfloat16(x1);
        __nv_bfloat16 l0 = __float2bfloat16(x0 - __bfloat162float(h0));
        __nv_bfloat16 l1 = __float2bfloat16(x1 - __bfloat162float(h1));
        dst[t]        = pack_bf16(h0, h1);
        dst[8064 + t] = pack_bf16(l0, l1);
    }
}

// ---------------------------------------------------------------------------
// Layer-1 scalar conv (ICH=1), packed f32x2, fused cpr partials (R12)
// ---------------------------------------------------------------------------
__global__ void __launch_bounds__(256, 2) conv3d1_kernel(
    const float* __restrict__ in, const float* __restrict__ wt,
    const float* __restrict__ bias, float* __restrict__ out,
    const float* __restrict__ alpha, float* __restrict__ featL)
{
    const int d0 = blockIdx.x * 8;
    const int b  = blockIdx.y;
    extern __shared__ float sm[];
    float*  w_s = sm;
    float2* in2 = (float2*)(sm + 63*16);
    __shared__ float alpha_s[128];
    const int tid = threadIdx.x;
    if (tid < 128) alpha_s[tid] = alpha[(tid >> 3)*128 + d0 + (tid & 7)];

    const int og = tid >> 7, pos = tid & 127;
    const int cpos = pos < HW ? pos : HW-1;
    const int h = cpos / 11, w = cpos - h*11;
    const int ppc = (h+1)*13 + (w+1);

    u64 acc[4][8];
    #pragma unroll
    for (int r = 0; r < 4; r++)
        #pragma unroll
        for (int o = 0; o < 8; o++) acc[r][o] = 0ULL;

    for (int t = tid; t < OCH*63; t += 256) { int o = t/63, r = t - o*63; w_s[r*16 + o] = wt[o*63 + r]; }
    for (int t = tid; t < 13*169; t += 256) {
        int dd = t/169, pp = t - dd*169;
        int h13 = pp/13, w13 = pp - h13*13, gd = d0 - 3 + dd;
        float v0 = 0.f, v1 = 0.f;
        if (h13 >= 1 && h13 <= 11 && w13 >= 1 && w13 <= 11) {
            const float* src = in + (size_t)b*DPT*HW + (h13-1)*11 + (w13-1);
            if (gd   >= 0 && gd   < DPT) v0 = src[(size_t)gd*HW];
            if (gd+1 >= 0 && gd+1 < DPT) v1 = src[(size_t)(gd+1)*HW];
        }
        in2[t] = make_float2(v0, v1);
    }
    __syncthreads();

    const u64*   col = (const u64*)in2 + ppc;
    const float* wb  = w_s + og*8;
    #pragma unroll 1
    for (int kd = 0; kd < 7; ++kd) {
        #pragma unroll
        for (int khw = 0; khw < 9; ++khw) {
            const int kh = khw/3, kw = khw - kh*3;
            const int off = (kh-1)*13 + (kw-1);
            const float* wk = wb + (kd*9 + khw)*16;
            float4 wa = *reinterpret_cast<const float4*>(wk);
            float4 wc = *reinterpret_cast<const float4*>(wk + 4);
            u64 wd[8] = {dup2(wa.x), dup2(wa.y), dup2(wa.z), dup2(wa.w),
                         dup2(wc.x), dup2(wc.y), dup2(wc.z), dup2(wc.w)};
            #pragma unroll
            for (int r = 0; r < 4; ++r) {
                u64 a = col[(kd + 2*r)*169 + off];
                #pragma unroll
                for (int o = 0; o < 8; ++o) acc[r][o] = fma2(a, wd[o], acc[r][o]);
            }
        }
    }

    if (pos < HW) {
        #pragma unroll
        for (int o = 0; o < 8; ++o) {
            const int oc = og*8 + o;
            const float bv = bias[oc];
            float* ob = out + ((size_t)(b*OCH + oc)*DPT + d0)*HW + pos;
            float fs = 0.f;
            #pragma unroll
            for (int r = 0; r < 4; ++r) {
                F2U a; a.u = acc[r][o];
                float v0 = fmaxf(a.f.x + bv, 0.f), v1 = fmaxf(a.f.y + bv, 0.f);
                ob[(2*r  )*HW] = v0;
                ob[(2*r+1)*HW] = v1;
                fs += alpha_s[oc*8 + 2*r]*v0 + alpha_s[oc*8 + 2*r + 1]*v1;
            }
            atomicAdd(&featL[b*FEAT_SZ + oc*HW + pos], fs);
        }
    }
}

// ---------------------------------------------------------------------------
// Layers 2/3: HMMA (mma.sync m16n8k16 bf16, 2-split, 3 passes).
// CTA = (b, d-block of 8). D[o=16, n=(d,p)=968] = sum_kk W[o,i]*X[i,n].
// X slab staged ONCE per CTA: [s2][dep14][pp169][i16] bf16. W pre-split.
// Per mma: 1 IADD + 2 LDS.32; A-frag hoisted per (pass, kk).
// ---------------------------------------------------------------------------
#define DEPS   5408        // 169*32 bytes per depth row
#define XSPL   75712       // 14*5408 per split
#define WOFFB  151424      // 2*XSPL
#define WSPLB  32256       // 63*512 per split
#define SMEM_CT (WOFFB + 2*WSPLB)   // 215936

template<bool WRITE_SA>
__global__ void __launch_bounds__(512, 1) convT2_kernel(
    const float* __restrict__ in, const u32* __restrict__ wsp,
    const float* __restrict__ bias, float* __restrict__ out,
    const float* __restrict__ alpha, float* __restrict__ featL)
{
    extern __shared__ char smx[];
    const int d0 = blockIdx.x * 8;
    const int b  = blockIdx.y;
    const int tid = threadIdx.x, wid = tid >> 5, l = tid & 31;

    // stage weights (contiguous, coalesced)
    {
        u32* wdst = (u32*)(smx + WOFFB);
        for (int t = tid; t < 16128; t += 512) wdst[t] = wsp[t];
    }
    // stage X slab: [dep][pp][i] with i-pair packed as u32, 2 splits
    for (int t = tid; t < 8*14*169; t += 512) {
        int ip  = t / (14*169);
        int r   = t - ip*(14*169);
        int dep = r / 169, pp = r - dep*169;
        int gd  = d0 - 3 + dep;
        int h13 = pp / 13, w13 = pp - h13*13;
        float x0 = 0.f, x1 = 0.f;
        if (gd >= 0 && gd < DPT && h13 >= 1 && h13 <= 11 && w13 >= 1 && w13 <= 11) {
            const float* src = in + ((size_t)(b*OCH + 2*ip)*DPT + gd)*HW + (h13-1)*11 + (w13-1);
            x0 = src[0];
            x1 = src[(size_t)DPT*HW];
        }
        __nv_bfloat16 h0 = __float2bfloat16(x0);
        __nv_bfloat16 h1 = __float2bfloat16(x1);
        __nv_bfloat16 l0 = __float2bfloat16(x0 - __bfloat162float(h0));
        __nv_bfloat16 l1 = __float2bfloat16(x1 - __bfloat162float(h1));
        int addr = dep*DEPS + pp*32 + ip*4;
        *(u32*)(smx + addr)        = pack_bf16(h0, h1);
        *(u32*)(smx + XSPL + addr) = pack_bf16(l0, l1);
    }
    __syncthreads();

    // per-lane B-address offsets per tile: tile T = wid + 16*k (T < 121)
    int coff[8];
    #pragma unroll
    for (int k = 0; k < 8; ++k) {
        int T = wid + 16*k;
        int Tc = T < 121 ? T : 120;
        int n  = Tc*8 + (l >> 2);
        int dl = n / 121, p = n - dl*121;
        int pp = (p/11 + 1)*13 + (p%11) + 1;
        coff[k] = dl*DEPS + pp*32 + (l & 3)*4;
    }
    const int aoff = (l >> 2)*32 + (l & 3)*4;

    float acc[8][4];
    #pragma unroll
    for (int k = 0; k < 8; ++k)
        #pragma unroll
        for (int q = 0; q < 4; ++q) acc[k][q] = 0.f;

    #pragma unroll 1
    for (int pass = 0; pass < 3; ++pass) {
        const char* Wb = smx + WOFFB + (pass == 1 ? WSPLB : 0);
        const char* Xb = smx + (pass == 2 ? XSPL : 0);
        #pragma unroll 1
        for (int kk = 0; kk < 63; ++kk) {
            const char* Wk = Wb + kk*512;
            u32 a0 = *(const u32*)(Wk + aoff);
            u32 a1 = *(const u32*)(Wk + aoff + 256);
            u32 a2 = *(const u32*)(Wk + aoff + 16);
            u32 a3 = *(const u32*)(Wk + aoff + 272);
            int kd = kk / 9, khw = kk - kd*9;
            int kh = khw / 3, kw = khw - kh*3;
            int uoff = kd*DEPS + ((kh-1)*13 + (kw-1))*32;
            const char* Xk = Xb + uoff;
            #pragma unroll
            for (int k = 0; k < 8; ++k) {
                if (k < 7 || wid < 9) {
                    u32 b0 = *(const u32*)(Xk + coff[k]);
                    u32 b1 = *(const u32*)(Xk + coff[k] + 16);
                    mma_bf16(acc[k], a0, a1, a2, a3, b0, b1);
                }
            }
        }
    }

    // epilogue: bias+relu, sa store, fused cpr partial (REDG)
    const int o0 = l >> 2, o1 = o0 + 8;
    const float bv0 = bias[o0], bv1 = bias[o1];
    #pragma unroll 1
    for (int k = 0; k < 8; ++k) {
        if (k < 7 || wid < 9) {
            int T = wid + 16*k;
            #pragma unroll
            for (int cc = 0; cc < 2; ++cc) {
                int nn = T*8 + (l & 3)*2 + cc;
                int dl = nn / 121, p = nn - dl*121;
                int gdo = d0 + dl;
                float v0 = fmaxf(acc[k][cc    ] + bv0, 0.f);
                float v1 = fmaxf(acc[k][cc + 2] + bv1, 0.f);
                if (WRITE_SA) {
                    out[((size_t)(b*OCH + o0)*DPT + gdo)*HW + p] = v0;
                    out[((size_t)(b*OCH + o1)*DPT + gdo)*HW + p] = v1;
                }
                atomicAdd(&featL[b*FEAT_SZ + o0*HW + p], alpha[o0*128 + gdo]*v0);
                atomicAdd(&featL[b*FEAT_SZ + o1*HW + p], alpha[o1*128 + gdo]*v1);
            }
        }
    }
}

// ---------------------------------------------------------------------------
__global__ void relu_kernel(float* x, int n)
{
    int t = blockIdx.x*blockDim.x + threadIdx.x;
    if (t < n) x[t] = fmaxf(x[t], 0.f);
}

__global__ void conv45_kernel(const float* __restrict__ feat2,
                              const float* __restrict__ w45, const float* __restrict__ b45,
                              float* __restrict__ feat3, float* __restrict__ feat4)
{
    const int b = blockIdx.x, tid = threadIdx.x;
    __shared__ float fa[FEAT_SZ], fb[FEAT_SZ];
    for (int t = tid; t < FEAT_SZ; t += 128) fa[t] = feat2[b*FEAT_SZ + t];
    __syncthreads();
    if (tid < HW) {
        int h = tid / 11, w = tid - h*11;
        for (int o = 0; o < 16; o++) {
            float acc = b45[o];
            for (int c = 0; c < 16; c++)
                for (int kh = 0; kh < 3; kh++) {
                    int hh = h + kh - 1; if (hh < 0 || hh >= 11) continue;
                    for (int kw = 0; kw < 3; kw++) {
                        int ww2 = w + kw - 1; if (ww2 < 0 || ww2 >= 11) continue;
                        acc += fa[c*HW + hh*11 + ww2] * w45[(o*16 + c)*9 + kh*3 + kw];
                    }
                }
            float v = fmaxf(acc, 0.f);
            fb[o*HW + tid] = v;
            feat3[b*FEAT_SZ + o*HW + tid] = v;
        }
    }
    __syncthreads();
    if (tid < HW) {
        int h = tid / 11, w = tid - h*11;
        for (int o = 0; o < 16; o++) {
            float acc = b45[16 + o];
            for (int c = 0; c < 16; c++)
                for (int kh = 0; kh < 3; kh++) {
                    int hh = h + kh - 1; if (hh < 0 || hh >= 11) continue;
                    for (int kw = 0; kw < 3; kw++) {
                        int ww2 = w + kw - 1; if (ww2 < 0 || ww2 >= 11) continue;
                        acc += fb[c*HW + hh*11 + ww2] * w45[2304 + (o*16 + c)*9 + kh*3 + kw];
                    }
                }
            feat4[b*FEAT_SZ + o*HW + tid] = fmaxf(acc, 0.f);
        }
    }
}

__global__ void side_kernel(const float* __restrict__ x, const float* __restrict__ feat,
    const float* __restrict__ sw,  const float* __restrict__ sb,
    const float* __restrict__ sow, const float* __restrict__ sob,
    const float* __restrict__ wa,  const float* __restrict__ ba,
    const float* __restrict__ wb,  const float* __restrict__ bbv,
    const float* __restrict__ ssw, const float* __restrict__ ssb,
    const float* __restrict__ fuse, float* __restrict__ out)
{
    const int i = blockIdx.x, b = blockIdx.y, tid = threadIdx.x;
    __shared__ float f_s[FEAT_SZ], act_s[HW], diff_s[HW], s_arr[128], xc[128], y1_s[144], y2_s[16];
    __shared__ int idx_s[5];

    for (int t = tid; t < FEAT_SZ; t += 128)
        f_s[t] = feat[i*(BB*FEAT_SZ) + b*FEAT_SZ + t];
    __syncthreads();

    if (tid < HW) {
        int h = tid / 11, w = tid - h*11;
        float acc = sb[i];
        for (int c = 0; c < 16; c++)
            for (int kh = 0; kh < 3; kh++) {
                int hh = h + kh - 1; if (hh < 0 || hh >= 11) continue;
                for (int kw = 0; kw < 3; kw++) {
                    int ww2 = w + kw - 1; if (ww2 < 0 || ww2 >= 11) continue;
                    acc += f_s[c*HW + hh*11 + ww2] * sw[(i*16 + c)*9 + kh*3 + kw];
                }
            }
        act_s[tid] = acc;
    }
    __syncthreads();
    if (tid < HW) diff_s[tid] = fabsf(act_s[tid] - act_s[60]);
    __syncthreads();
    if (tid == 0) {
        for (int j = 0; j < 5; j++) {
            float best = 3.4e38f; int bi = 0;
            for (int p = 0; p < HW; p++) { float d = diff_s[p]; if (d < best) { best = d; bi = p; } }
            idx_s[j] = bi; diff_s[bi] = 3.4e38f;
        }
    }
    __syncthreads();
    {
        float s = 0.f;
        const float* xb = x + (size_t)(b*128 + tid)*HW;
        #pragma unroll
        for (int j = 0; j < 5; j++) s += xb[idx_s[j]];
        s_arr[tid] = s;
        xc[tid] = xb[60];
    }
    __syncthreads();
    for (int t = tid; t < 144; t += 128) {
        int o = t / 9, j = t - o*9;
        int pj = 62 + 2*(j/3), qj = 62 + 2*(j%3);
        float acc = ba[i*16 + o];
        #pragma unroll
        for (int ch = 0; ch < 2; ch++) {
            const float* num = ch ? xc : s_arr;
            #pragma unroll
            for (int eh = 0; eh < 3; eh++)
                #pragma unroll
                for (int ew = 0; ew < 3; ew++) {
                    int r = pj + eh - 1, c = qj + ew - 1;
                    float den = num[c];
                    den = fabsf(den) < 0.01f ? 0.01f : den;
                    acc += (num[r] / den) * wa[(((i*16 + o)*2 + ch)*3 + eh)*3 + ew];
                }
        }
        y1_s[o*9 + j] = fmaxf(acc, 0.f);
    }
    __syncthreads();
    if (tid < 16) {
        float acc = bbv[i*16 + tid];
        for (int c = 0; c < 16; c++)
            #pragma unroll
            for (int j = 0; j < 9; j++)
                acc += y1_s[c*9 + j] * wb[((i*16 + tid)*16 + c)*9 + j];
        y2_s[tid] = fmaxf(acc, 0.f);
    }
    __syncthreads();
    if (tid < 16) {
        float sa_v = sob[i*16 + tid];
        for (int k = 0; k < 16; k++) sa_v += f_s[k*HW + 60] * sow[(i*16 + tid)*16 + k];
        float sp_v = ssb[i*16 + tid];
        for (int c = 0; c < 16; c++) sp_v += y2_s[c] * ssw[(i*16 + tid)*16 + c];
        atomicAdd(&out[b*16 + tid], fuse[i]*sa_v + fuse[5 + i]*sp_v);
    }
}

__global__ void zero_kernel(float* out, int n)
{
    int t = blockIdx.x*blockDim.x + threadIdx.x;
    if (t < n) out[t] = 0.f;
}

// ---------------------------------------------------------------------------
extern "C" void kernel_launch(void* const* d_in, const int* in_sizes, int n_in,
                              void* d_out, int out_size)
{
    const float* x      = (const float*)d_in[0];
    const float* w3d1   = (const float*)d_in[1];
    const float* b3d1   = (const float*)d_in[2];
    const float* w3d23  = (const float*)d_in[3];
    const float* b3d23  = (const float*)d_in[4];
    const float* cpr_w  = (const float*)d_in[5];
    const float* w2d45  = (const float*)d_in[6];
    const float* b2d45  = (const float*)d_in[7];
    const float* seg_w  = (const float*)d_in[8];
    const float* seg_b  = (const float*)d_in[9];
    const float* so_w   = (const float*)d_in[10];
    const float* so_b   = (const float*)d_in[11];
    const float* sp_wa  = (const float*)d_in[12];
    const float* sp_ba  = (const float*)d_in[13];
    const float* sp_wb  = (const float*)d_in[14];
    const float* sp_bb  = (const float*)d_in[15];
    const float* sp_sw  = (const float*)d_in[16];
    const float* sp_sb  = (const float*)d_in[17];
    const float* fuse   = (const float*)d_in[18];
    float* out = (float*)d_out;

    float *sa1, *sa2, *feat, *alpha;
    u32* wsp;
    cudaGetSymbolAddress((void**)&sa1,   g_sa1);
    cudaGetSymbolAddress((void**)&sa2,   g_sa2);
    cudaGetSymbolAddress((void**)&feat,  g_feat);
    cudaGetSymbolAddress((void**)&alpha, g_alpha);
    cudaGetSymbolAddress((void**)&wsp,   g_wsplit);

    const int SMEM1 = 63*16*4 + 13*169*8;
    cudaFuncSetAttribute((const void*)conv3d1_kernel, cudaFuncAttributeMaxDynamicSharedMemorySize, SMEM1);
    cudaFuncSetAttribute((const void*)convT2_kernel<true>,  cudaFuncAttributeMaxDynamicSharedMemorySize, SMEM_CT);
    cudaFuncSetAttribute((const void*)convT2_kernel<false>, cudaFuncAttributeMaxDynamicSharedMemorySize, SMEM_CT);

    alpha_kernel<<<48, 128>>>(cpr_w, alpha);
    wsplit_kernel<<<32, 256>>>(w3d23,         wsp);
    wsplit_kernel<<<32, 256>>>(w3d23 + 16128, wsp + 16128);
    zero_kernel<<<(out_size + 255)/256, 256>>>(out, out_size);
    zero_kernel<<<(3*BB*FEAT_SZ + 255)/256, 256>>>(feat, 3*BB*FEAT_SZ);

    conv3d1_kernel<<<dim3(16, BB), 256, SMEM1>>>(
        x, w3d1, b3d1, sa1, alpha + 0*2048, feat + 0*(BB*FEAT_SZ));

    convT2_kernel<true><<<dim3(16, BB), 512, SMEM_CT>>>(
        sa1, wsp, b3d23, sa2, alpha + 1*2048, feat + 1*(BB*FEAT_SZ));

    convT2_kernel<false><<<dim3(16, BB), 512, SMEM_CT>>>(
        sa2, wsp + 16128, b3d23 + 16, sa1 /*unused*/, alpha + 2*2048, feat + 2*(BB*FEAT_SZ));

    relu_kernel<<<(3*BB*FEAT_SZ + 255)/256, 256>>>(feat, 3*BB*FEAT_SZ);

    conv45_kernel<<<BB, 128>>>(feat + 2*(BB*FEAT_SZ), w2d45, b2d45,
                               feat + 3*(BB*FEAT_SZ), feat + 4*(BB*FEAT_SZ));

    side_kernel<<<dim3(5, BB), 128>>>(x, feat, seg_w, seg_b, so_w, so_b,
                                      sp_wa, sp_ba, sp_wb, sp_bb, sp_sw, sp_sb,
                                      fuse, out);
}

// round 14
// speedup vs baseline: 3.4906x; 1.3800x over previous
#include <cuda_runtime.h>
#include <cuda_bf16.h>

#define BB   64
#define DPT  128
#define HW   121
#define OCH  16
#define FEAT_SZ (OCH*HW)

typedef unsigned long long u64;
typedef unsigned int u32;
union F2U { u64 u; float2 f; };

__device__ __forceinline__ u64 fma2(u64 a, u64 b, u64 c) {
    u64 d; asm("fma.rn.f32x2 %0, %1, %2, %3;" : "=l"(d) : "l"(a), "l"(b), "l"(c)); return d;
}
__device__ __forceinline__ u64 dup2(float w) {
    u64 d; asm("mov.b64 %0, {%1, %1};" : "=l"(d) : "f"(w)); return d;
}
__device__ __forceinline__ void mma_bf16(float (&c)[4], u32 a0, u32 a1, u32 a2, u32 a3,
                                         u32 b0, u32 b1) {
    asm volatile("mma.sync.aligned.m16n8k16.row.col.f32.bf16.bf16.f32 "
        "{%0,%1,%2,%3}, {%4,%5,%6,%7}, {%8,%9}, {%0,%1,%2,%3};"
        : "+f"(c[0]), "+f"(c[1]), "+f"(c[2]), "+f"(c[3])
        : "r"(a0), "r"(a1), "r"(a2), "r"(a3), "r"(b0), "r"(b1));
}
__device__ __forceinline__ u32 pack_bf16(__nv_bfloat16 lo, __nv_bfloat16 hi) {
    __nv_bfloat162 t = __nv_bfloat162(lo, hi);
    return *reinterpret_cast<u32*>(&t);
}

__device__ float g_sa1[BB*OCH*DPT*HW];
__device__ float g_sa2[BB*OCH*DPT*HW];
__device__ float g_feat[5*BB*OCH*HW];
__device__ float g_alpha[3*OCH*DPT];
__device__ u32   g_wsplit[2*16128];

// ---------------------------------------------------------------------------
// prep: alpha softmax (blocks 0..47), weight split both layers (48..111),
// zero out (112..115), zero feat (116..). One launch.
// W split layout (per layer, per split s): u32 idx = kk*128 + o*8 + q*2 + half
//   value = pair(i = 2q+8*half, 2q+1+8*half) of bf16 (hi split s=0, lo s=1 at +8064)
// ---------------------------------------------------------------------------
__global__ void prep_kernel(const float* __restrict__ cw, const float* __restrict__ w3d23,
                            float* __restrict__ alpha, u32* __restrict__ wsp,
                            float* __restrict__ out, int out_n, float* __restrict__ feat)
{
    const int bid = blockIdx.x, tid = threadIdx.x;
    if (bid < 48) {
        __shared__ float red[128];
        float wv = 0.f, e = 0.f;
        if (tid < 128) { wv = cw[bid*128 + tid]; red[tid] = wv; }
        __syncthreads();
        for (int s = 64; s > 0; s >>= 1) { if (tid < s) red[tid] = fmaxf(red[tid], red[tid+s]); __syncthreads(); }
        float mx = red[0]; __syncthreads();
        if (tid < 128) { e = expf(wv - mx); red[tid] = e; }
        __syncthreads();
        for (int s = 64; s > 0; s >>= 1) { if (tid < s) red[tid] += red[tid+s]; __syncthreads(); }
        if (tid < 128) alpha[bid*128 + tid] = e / red[0];
    } else if (bid < 112) {
        int g = (bid - 48)*256 + tid;
        if (g < 16128) {
            int layer = g / 8064, tt = g - layer*8064;
            int kk = tt >> 7, r = tt & 127;
            int o = r >> 3, s2 = r & 7;
            int q = s2 >> 1, half = s2 & 1;
            const float* wt = w3d23 + layer*16128;
            int c0 = 2*q + 8*half;
            float x0 = wt[o*1008 + c0*63 + kk];
            float x1 = wt[o*1008 + (c0+1)*63 + kk];
            __nv_bfloat16 h0 = __float2bfloat16(x0);
            __nv_bfloat16 h1 = __float2bfloat16(x1);
            __nv_bfloat16 l0 = __float2bfloat16(x0 - __bfloat162float(h0));
            __nv_bfloat16 l1 = __float2bfloat16(x1 - __bfloat162float(h1));
            u32* dst = wsp + layer*16128;
            dst[tt]        = pack_bf16(h0, h1);
            dst[8064 + tt] = pack_bf16(l0, l1);
        }
    } else if (bid < 116) {
        int g = (bid - 112)*256 + tid;
        if (g < out_n) out[g] = 0.f;
    } else {
        int g = (bid - 116)*256 + tid;
        if (g < 3*BB*FEAT_SZ) feat[g] = 0.f;
    }
}

// ---------------------------------------------------------------------------
// Layer-1 scalar conv (ICH=1), packed f32x2, fused cpr partials
// ---------------------------------------------------------------------------
__global__ void __launch_bounds__(256, 2) conv3d1_kernel(
    const float* __restrict__ in, const float* __restrict__ wt,
    const float* __restrict__ bias, float* __restrict__ out,
    const float* __restrict__ alpha, float* __restrict__ featL)
{
    const int d0 = blockIdx.x * 8;
    const int b  = blockIdx.y;
    extern __shared__ float sm[];
    float*  w_s = sm;
    float2* in2 = (float2*)(sm + 63*16);
    __shared__ float alpha_s[128];
    const int tid = threadIdx.x;
    if (tid < 128) alpha_s[tid] = alpha[(tid >> 3)*128 + d0 + (tid & 7)];

    const int og = tid >> 7, pos = tid & 127;
    const int cpos = pos < HW ? pos : HW-1;
    const int h = cpos / 11, w = cpos - h*11;
    const int ppc = (h+1)*13 + (w+1);

    u64 acc[4][8];
    #pragma unroll
    for (int r = 0; r < 4; r++)
        #pragma unroll
        for (int o = 0; o < 8; o++) acc[r][o] = 0ULL;

    for (int t = tid; t < OCH*63; t += 256) { int o = t/63, r = t - o*63; w_s[r*16 + o] = wt[o*63 + r]; }
    for (int t = tid; t < 13*169; t += 256) {
        int dd = t/169, pp = t - dd*169;
        int h13 = pp/13, w13 = pp - h13*13, gd = d0 - 3 + dd;
        float v0 = 0.f, v1 = 0.f;
        if (h13 >= 1 && h13 <= 11 && w13 >= 1 && w13 <= 11) {
            const float* src = in + (size_t)b*DPT*HW + (h13-1)*11 + (w13-1);
            if (gd   >= 0 && gd   < DPT) v0 = src[(size_t)gd*HW];
            if (gd+1 >= 0 && gd+1 < DPT) v1 = src[(size_t)(gd+1)*HW];
        }
        in2[t] = make_float2(v0, v1);
    }
    __syncthreads();

    const u64*   col = (const u64*)in2 + ppc;
    const float* wb  = w_s + og*8;
    #pragma unroll 1
    for (int kd = 0; kd < 7; ++kd) {
        #pragma unroll
        for (int khw = 0; khw < 9; ++khw) {
            const int kh = khw/3, kw = khw - kh*3;
            const int off = (kh-1)*13 + (kw-1);
            const float* wk = wb + (kd*9 + khw)*16;
            float4 wa = *reinterpret_cast<const float4*>(wk);
            float4 wc = *reinterpret_cast<const float4*>(wk + 4);
            u64 wd[8] = {dup2(wa.x), dup2(wa.y), dup2(wa.z), dup2(wa.w),
                         dup2(wc.x), dup2(wc.y), dup2(wc.z), dup2(wc.w)};
            #pragma unroll
            for (int r = 0; r < 4; ++r) {
                u64 a = col[(kd + 2*r)*169 + off];
                #pragma unroll
                for (int o = 0; o < 8; ++o) acc[r][o] = fma2(a, wd[o], acc[r][o]);
            }
        }
    }

    if (pos < HW) {
        #pragma unroll
        for (int o = 0; o < 8; ++o) {
            const int oc = og*8 + o;
            const float bv = bias[oc];
            float* ob = out + ((size_t)(b*OCH + oc)*DPT + d0)*HW + pos;
            float fs = 0.f;
            #pragma unroll
            for (int r = 0; r < 4; ++r) {
                F2U a; a.u = acc[r][o];
                float v0 = fmaxf(a.f.x + bv, 0.f), v1 = fmaxf(a.f.y + bv, 0.f);
                ob[(2*r  )*HW] = v0;
                ob[(2*r+1)*HW] = v1;
                fs += alpha_s[oc*8 + 2*r]*v0 + alpha_s[oc*8 + 2*r + 1]*v1;
            }
            atomicAdd(&featL[b*FEAT_SZ + oc*HW + pos], fs);
        }
    }
}

// ---------------------------------------------------------------------------
// Layers 2/3: HMMA, interleaved fragment layout (LDS.64 operand loads).
// X row per (dep,pp) = 32B: q-major, [pair(2q,2q+1) | pair(2q+8,2q+9)] at q*8.
// W row per kk = 512B: o*32 + q*8, same interleave; o+8 block at +256.
// Per kk per warp: 2 LDS.64 (A) + 8 LDS.64 (B) + 8 mma; k=7 tile guarded once.
// ---------------------------------------------------------------------------
#define DEPS   5408
#define XSPL   75712
#define WOFFB  151424
#define WSPLB  32256
#define SMEM_CT (WOFFB + 2*WSPLB)

template<bool WRITE_SA>
__global__ void __launch_bounds__(512, 1) convT2_kernel(
    const float* __restrict__ in, const u32* __restrict__ wsp,
    const float* __restrict__ bias, float* __restrict__ out,
    const float* __restrict__ alpha, float* __restrict__ featL)
{
    extern __shared__ char smx[];
    const int d0 = blockIdx.x * 8;
    const int b  = blockIdx.y;
    const int tid = threadIdx.x, wid = tid >> 5, l = tid & 31;

    {
        u32* wdst = (u32*)(smx + WOFFB);
        for (int t = tid; t < 16128; t += 512) wdst[t] = wsp[t];
    }
    // X slab: iq = (q, half); channels (2q+8h, 2q+1+8h); addr pp*32 + q*8 + h*4
    for (int t = tid; t < 8*14*169; t += 512) {
        int iq  = t / (14*169);
        int r   = t - iq*(14*169);
        int dep = r / 169, pp = r - dep*169;
        int q = iq >> 1, half = iq & 1;
        int gd  = d0 - 3 + dep;
        int h13 = pp / 13, w13 = pp - h13*13;
        float x0 = 0.f, x1 = 0.f;
        if (gd >= 0 && gd < DPT && h13 >= 1 && h13 <= 11 && w13 >= 1 && w13 <= 11) {
            int c0 = 2*q + 8*half;
            const float* src = in + ((size_t)(b*OCH + c0)*DPT + gd)*HW + (h13-1)*11 + (w13-1);
            x0 = src[0];
            x1 = src[(size_t)DPT*HW];
        }
        __nv_bfloat16 h0 = __float2bfloat16(x0);
        __nv_bfloat16 h1 = __float2bfloat16(x1);
        __nv_bfloat16 l0 = __float2bfloat16(x0 - __bfloat162float(h0));
        __nv_bfloat16 l1 = __float2bfloat16(x1 - __bfloat162float(h1));
        int addr = dep*DEPS + pp*32 + q*8 + half*4;
        *(u32*)(smx + addr)        = pack_bf16(h0, h1);
        *(u32*)(smx + XSPL + addr) = pack_bf16(l0, l1);
    }
    __syncthreads();

    // per-lane B offsets; tile T = wid + 16*k
    int coff[8];
    #pragma unroll
    for (int k = 0; k < 8; ++k) {
        int T = wid + 16*k;
        int Tc = T < 121 ? T : 120;
        int n  = Tc*8 + (l >> 2);
        int dl = n / 121, p = n - dl*121;
        int pp = (p/11 + 1)*13 + (p%11) + 1;
        coff[k] = dl*DEPS + pp*32 + (l & 3)*8;
    }
    const int aoff = (l >> 2)*32 + (l & 3)*8;

    float acc[8][4];
    #pragma unroll
    for (int k = 0; k < 8; ++k)
        #pragma unroll
        for (int q = 0; q < 4; ++q) acc[k][q] = 0.f;

    const bool last_ok = (wid < 9);
    #pragma unroll 1
    for (int pass = 0; pass < 3; ++pass) {
        const char* Wb = smx + WOFFB + (pass == 1 ? WSPLB : 0);
        const char* Xb = smx + (pass == 2 ? XSPL : 0);
        #pragma unroll 1
        for (int kk = 0; kk < 63; ++kk) {
            const char* Wk = Wb + kk*512;
            u64 a02 = *(const u64*)(Wk + aoff);
            u64 a13 = *(const u64*)(Wk + aoff + 256);
            u32 a0 = (u32)a02, a2 = (u32)(a02 >> 32);
            u32 a1 = (u32)a13, a3 = (u32)(a13 >> 32);
            int kd = kk / 9, khw = kk - kd*9;
            int kh = khw / 3, kw = khw - kh*3;
            const char* Xk = Xb + kd*DEPS + ((kh-1)*13 + (kw-1))*32;
            #pragma unroll
            for (int k = 0; k < 7; ++k) {
                u64 b01 = *(const u64*)(Xk + coff[k]);
                mma_bf16(acc[k], a0, a1, a2, a3, (u32)b01, (u32)(b01 >> 32));
            }
            if (last_ok) {
                u64 b01 = *(const u64*)(Xk + coff[7]);
                mma_bf16(acc[7], a0, a1, a2, a3, (u32)b01, (u32)(b01 >> 32));
            }
        }
    }

    // epilogue: bias+relu, sa store, fused cpr partial (atomics)
    const int o0 = l >> 2, o1 = o0 + 8;
    const float bv0 = bias[o0], bv1 = bias[o1];
    #pragma unroll 1
    for (int k = 0; k < 8; ++k) {
        if (k < 7 || last_ok) {
            int T = wid + 16*k;
            #pragma unroll
            for (int cc = 0; cc < 2; ++cc) {
                int nn = T*8 + (l & 3)*2 + cc;
                int dl = nn / 121, p = nn - dl*121;
                int gdo = d0 + dl;
                float v0 = fmaxf(acc[k][cc    ] + bv0, 0.f);
                float v1 = fmaxf(acc[k][cc + 2] + bv1, 0.f);
                if (WRITE_SA) {
                    out[((size_t)(b*OCH + o0)*DPT + gdo)*HW + p] = v0;
                    out[((size_t)(b*OCH + o1)*DPT + gdo)*HW + p] = v1;
                }
                atomicAdd(&featL[b*FEAT_SZ + o0*HW + p], alpha[o0*128 + gdo]*v0);
                atomicAdd(&featL[b*FEAT_SZ + o1*HW + p], alpha[o1*128 + gdo]*v1);
            }
        }
    }
}

// ---------------------------------------------------------------------------
__global__ void relu_kernel(float* x, int n)
{
    int t = blockIdx.x*blockDim.x + threadIdx.x;
    if (t < n) x[t] = fmaxf(x[t], 0.f);
}

__global__ void conv45_kernel(const float* __restrict__ feat2,
                              const float* __restrict__ w45, const float* __restrict__ b45,
                              float* __restrict__ feat3, float* __restrict__ feat4)
{
    const int b = blockIdx.x, tid = threadIdx.x;
    __shared__ float fa[FEAT_SZ], fb[FEAT_SZ];
    for (int t = tid; t < FEAT_SZ; t += 128) fa[t] = feat2[b*FEAT_SZ + t];
    __syncthreads();
    if (tid < HW) {
        int h = tid / 11, w = tid - h*11;
        for (int o = 0; o < 16; o++) {
            float acc = b45[o];
            for (int c = 0; c < 16; c++)
                for (int kh = 0; kh < 3; kh++) {
                    int hh = h + kh - 1; if (hh < 0 || hh >= 11) continue;
                    for (int kw = 0; kw < 3; kw++) {
                        int ww2 = w + kw - 1; if (ww2 < 0 || ww2 >= 11) continue;
                        acc += fa[c*HW + hh*11 + ww2] * w45[(o*16 + c)*9 + kh*3 + kw];
                    }
                }
            float v = fmaxf(acc, 0.f);
            fb[o*HW + tid] = v;
            feat3[b*FEAT_SZ + o*HW + tid] = v;
        }
    }
    __syncthreads();
    if (tid < HW) {
        int h = tid / 11, w = tid - h*11;
        for (int o = 0; o < 16; o++) {
            float acc = b45[16 + o];
            for (int c = 0; c < 16; c++)
                for (int kh = 0; kh < 3; kh++) {
                    int hh = h + kh - 1; if (hh < 0 || hh >= 11) continue;
                    for (int kw = 0; kw < 3; kw++) {
                        int ww2 = w + kw - 1; if (ww2 < 0 || ww2 >= 11) continue;
                        acc += fb[c*HW + hh*11 + ww2] * w45[2304 + (o*16 + c)*9 + kh*3 + kw];
                    }
                }
            feat4[b*FEAT_SZ + o*HW + tid] = fmaxf(acc, 0.f);
        }
    }
}

__global__ void side_kernel(const float* __restrict__ x, const float* __restrict__ feat,
    const float* __restrict__ sw,  const float* __restrict__ sb,
    const float* __restrict__ sow, const float* __restrict__ sob,
    const float* __restrict__ wa,  const float* __restrict__ ba,
    const float* __restrict__ wb,  const float* __restrict__ bbv,
    const float* __restrict__ ssw, const float* __restrict__ ssb,
    const float* __restrict__ fuse, float* __restrict__ out)
{
    const int i = blockIdx.x, b = blockIdx.y, tid = threadIdx.x;
    __shared__ float f_s[FEAT_SZ], act_s[HW], diff_s[HW], s_arr[128], xc[128], y1_s[144], y2_s[16];
    __shared__ int idx_s[5];

    for (int t = tid; t < FEAT_SZ; t += 128)
        f_s[t] = feat[i*(BB*FEAT_SZ) + b*FEAT_SZ + t];
    __syncthreads();

    if (tid < HW) {
        int h = tid / 11, w = tid - h*11;
        float acc = sb[i];
        for (int c = 0; c < 16; c++)
            for (int kh = 0; kh < 3; kh++) {
                int hh = h + kh - 1; if (hh < 0 || hh >= 11) continue;
                for (int kw = 0; kw < 3; kw++) {
                    int ww2 = w + kw - 1; if (ww2 < 0 || ww2 >= 11) continue;
                    acc += f_s[c*HW + hh*11 + ww2] * sw[(i*16 + c)*9 + kh*3 + kw];
                }
            }
        act_s[tid] = acc;
    }
    __syncthreads();
    if (tid < HW) diff_s[tid] = fabsf(act_s[tid] - act_s[60]);
    __syncthreads();
    if (tid == 0) {
        for (int j = 0; j < 5; j++) {
            float best = 3.4e38f; int bi = 0;
            for (int p = 0; p < HW; p++) { float d = diff_s[p]; if (d < best) { best = d; bi = p; } }
            idx_s[j] = bi; diff_s[bi] = 3.4e38f;
        }
    }
    __syncthreads();
    {
        float s = 0.f;
        const float* xb = x + (size_t)(b*128 + tid)*HW;
        #pragma unroll
        for (int j = 0; j < 5; j++) s += xb[idx_s[j]];
        s_arr[tid] = s;
        xc[tid] = xb[60];
    }
    __syncthreads();
    for (int t = tid; t < 144; t += 128) {
        int o = t / 9, j = t - o*9;
        int pj = 62 + 2*(j/3), qj = 62 + 2*(j%3);
        float acc = ba[i*16 + o];
        #pragma unroll
        for (int ch = 0; ch < 2; ch++) {
            const float* num = ch ? xc : s_arr;
            #pragma unroll
            for (int eh = 0; eh < 3; eh++)
                #pragma unroll
                for (int ew = 0; ew < 3; ew++) {
                    int r = pj + eh - 1, c = qj + ew - 1;
                    float den = num[c];
                    den = fabsf(den) < 0.01f ? 0.01f : den;
                    acc += (num[r] / den) * wa[(((i*16 + o)*2 + ch)*3 + eh)*3 + ew];
                }
        }
        y1_s[o*9 + j] = fmaxf(acc, 0.f);
    }
    __syncthreads();
    if (tid < 16) {
        float acc = bbv[i*16 + tid];
        for (int c = 0; c < 16; c++)
            #pragma unroll
            for (int j = 0; j < 9; j++)
                acc += y1_s[c*9 + j] * wb[((i*16 + tid)*16 + c)*9 + j];
        y2_s[tid] = fmaxf(acc, 0.f);
    }
    __syncthreads();
    if (tid < 16) {
        float sa_v = sob[i*16 + tid];
        for (int k = 0; k < 16; k++) sa_v += f_s[k*HW + 60] * sow[(i*16 + tid)*16 + k];
        float sp_v = ssb[i*16 + tid];
        for (int c = 0; c < 16; c++) sp_v += y2_s[c] * ssw[(i*16 + tid)*16 + c];
        atomicAdd(&out[b*16 + tid], fuse[i]*sa_v + fuse[5 + i]*sp_v);
    }
}

// ---------------------------------------------------------------------------
extern "C" void kernel_launch(void* const* d_in, const int* in_sizes, int n_in,
                              void* d_out, int out_size)
{
    const float* x      = (const float*)d_in[0];
    const float* w3d1   = (const float*)d_in[1];
    const float* b3d1   = (const float*)d_in[2];
    const float* w3d23  = (const float*)d_in[3];
    const float* b3d23  = (const float*)d_in[4];
    const float* cpr_w  = (const float*)d_in[5];
    const float* w2d45  = (const float*)d_in[6];
    const float* b2d45  = (const float*)d_in[7];
    const float* seg_w  = (const float*)d_in[8];
    const float* seg_b  = (const float*)d_in[9];
    const float* so_w   = (const float*)d_in[10];
    const float* so_b   = (const float*)d_in[11];
    const float* sp_wa  = (const float*)d_in[12];
    const float* sp_ba  = (const float*)d_in[13];
    const float* sp_wb  = (const float*)d_in[14];
    const float* sp_bb  = (const float*)d_in[15];
    const float* sp_sw  = (const float*)d_in[16];
    const float* sp_sb  = (const float*)d_in[17];
    const float* fuse   = (const float*)d_in[18];
    float* out = (float*)d_out;

    float *sa1, *sa2, *feat, *alpha;
    u32* wsp;
    cudaGetSymbolAddress((void**)&sa1,   g_sa1);
    cudaGetSymbolAddress((void**)&sa2,   g_sa2);
    cudaGetSymbolAddress((void**)&feat,  g_feat);
    cudaGetSymbolAddress((void**)&alpha, g_alpha);
    cudaGetSymbolAddress((void**)&wsp,   g_wsplit);

    const int SMEM1 = 63*16*4 + 13*169*8;
    cudaFuncSetAttribute((const void*)conv3d1_kernel, cudaFuncAttributeMaxDynamicSharedMemorySize, SMEM1);
    cudaFuncSetAttribute((const void*)convT2_kernel<true>,  cudaFuncAttributeMaxDynamicSharedMemorySize, SMEM_CT);
    cudaFuncSetAttribute((const void*)convT2_kernel<false>, cudaFuncAttributeMaxDynamicSharedMemorySize, SMEM_CT);

    // launch order chosen so convT2<false> is the 4th launch (ncu captures #4)
    const int prep_blocks = 116 + (3*BB*FEAT_SZ + 255)/256;
    prep_kernel<<<prep_blocks, 256>>>(cpr_w, w3d23, alpha, wsp, out, out_size, feat);

    conv3d1_kernel<<<dim3(16, BB), 256, SMEM1>>>(
        x, w3d1, b3d1, sa1, alpha + 0*2048, feat + 0*(BB*FEAT_SZ));

    convT2_kernel<true><<<dim3(16, BB), 512, SMEM_CT>>>(
        sa1, wsp, b3d23, sa2, alpha + 1*2048, feat + 1*(BB*FEAT_SZ));

    convT2_kernel<false><<<dim3(16, BB), 512, SMEM_CT>>>(
        sa2, wsp + 16128, b3d23 + 16, sa1 /*unused*/, alpha + 2*2048, feat + 2*(BB*FEAT_SZ));

    relu_kernel<<<(3*BB*FEAT_SZ + 255)/256, 256>>>(feat, 3*BB*FEAT_SZ);

    conv45_kernel<<<BB, 128>>>(feat + 2*(BB*FEAT_SZ), w2d45, b2d45,
                               feat + 3*(BB*FEAT_SZ), feat + 4*(BB*FEAT_SZ));

    side_kernel<<<dim3(5, BB), 128>>>(x, feat, seg_w, seg_b, so_w, so_b,
                                      sp_wa, sp_ba, sp_wb, sp_bb, sp_sw, sp_sb,
                                      fuse, out);
}

// round 15
// speedup vs baseline: 4.1819x; 1.1980x over previous
#include <cuda_runtime.h>
#include <cuda_bf16.h>

#define BB   64
#define DPT  128
#define HW   121
#define OCH  16
#define FEAT_SZ (OCH*HW)

typedef unsigned long long u64;
typedef unsigned int u32;
union F2U { u64 u; float2 f; };

__device__ __forceinline__ u64 fma2(u64 a, u64 b, u64 c) {
    u64 d; asm("fma.rn.f32x2 %0, %1, %2, %3;" : "=l"(d) : "l"(a), "l"(b), "l"(c)); return d;
}
__device__ __forceinline__ u64 dup2(float w) {
    u64 d; asm("mov.b64 %0, {%1, %1};" : "=l"(d) : "f"(w)); return d;
}
__device__ __forceinline__ void mma_bf16(float (&c)[4], u32 a0, u32 a1, u32 a2, u32 a3,
                                         u32 b0, u32 b1) {
    asm volatile("mma.sync.aligned.m16n8k16.row.col.f32.bf16.bf16.f32 "
        "{%0,%1,%2,%3}, {%4,%5,%6,%7}, {%8,%9}, {%0,%1,%2,%3};"
        : "+f"(c[0]), "+f"(c[1]), "+f"(c[2]), "+f"(c[3])
        : "r"(a0), "r"(a1), "r"(a2), "r"(a3), "r"(b0), "r"(b1));
}
__device__ __forceinline__ u32 pack_bf16(__nv_bfloat16 lo, __nv_bfloat16 hi) {
    __nv_bfloat162 t = __nv_bfloat162(lo, hi);
    return *reinterpret_cast<u32*>(&t);
}

__device__ float g_sa1[BB*OCH*DPT*HW];
__device__ float g_sa2[BB*OCH*DPT*HW];
__device__ float g_feat[5*BB*OCH*HW];
__device__ float g_alpha[3*OCH*DPT];
__device__ u32   g_wsplit[2*16128];

// ---------------------------------------------------------------------------
// prep: alpha softmax (blocks 0..47), weight split both layers (48..111),
// zero out (112..115), zero feat (116..). One launch.
// ---------------------------------------------------------------------------
__global__ void prep_kernel(const float* __restrict__ cw, const float* __restrict__ w3d23,
                            float* __restrict__ alpha, u32* __restrict__ wsp,
                            float* __restrict__ out, int out_n, float* __restrict__ feat)
{
    const int bid = blockIdx.x, tid = threadIdx.x;
    if (bid < 48) {
        __shared__ float red[128];
        float wv = 0.f, e = 0.f;
        if (tid < 128) { wv = cw[bid*128 + tid]; red[tid] = wv; }
        __syncthreads();
        for (int s = 64; s > 0; s >>= 1) { if (tid < s) red[tid] = fmaxf(red[tid], red[tid+s]); __syncthreads(); }
        float mx = red[0]; __syncthreads();
        if (tid < 128) { e = expf(wv - mx); red[tid] = e; }
        __syncthreads();
        for (int s = 64; s > 0; s >>= 1) { if (tid < s) red[tid] += red[tid+s]; __syncthreads(); }
        if (tid < 128) alpha[bid*128 + tid] = e / red[0];
    } else if (bid < 112) {
        int g = (bid - 48)*256 + tid;
        if (g < 16128) {
            int layer = g / 8064, tt = g - layer*8064;
            int kk = tt >> 7, r = tt & 127;
            int o = r >> 3, s2 = r & 7;
            int q = s2 >> 1, half = s2 & 1;
            const float* wt = w3d23 + layer*16128;
            int c0 = 2*q + 8*half;
            float x0 = wt[o*1008 + c0*63 + kk];
            float x1 = wt[o*1008 + (c0+1)*63 + kk];
            __nv_bfloat16 h0 = __float2bfloat16(x0);
            __nv_bfloat16 h1 = __float2bfloat16(x1);
            __nv_bfloat16 l0 = __float2bfloat16(x0 - __bfloat162float(h0));
            __nv_bfloat16 l1 = __float2bfloat16(x1 - __bfloat162float(h1));
            u32* dst = wsp + layer*16128;
            dst[tt]        = pack_bf16(h0, h1);
            dst[8064 + tt] = pack_bf16(l0, l1);
        }
    } else if (bid < 116) {
        int g = (bid - 112)*256 + tid;
        if (g < out_n) out[g] = 0.f;
    } else {
        int g = (bid - 116)*256 + tid;
        if (g < 3*BB*FEAT_SZ) feat[g] = 0.f;
    }
}

// ---------------------------------------------------------------------------
// Layer-1 scalar conv (ICH=1), packed f32x2, fused cpr partials
// ---------------------------------------------------------------------------
__global__ void __launch_bounds__(256, 2) conv3d1_kernel(
    const float* __restrict__ in, const float* __restrict__ wt,
    const float* __restrict__ bias, float* __restrict__ out,
    const float* __restrict__ alpha, float* __restrict__ featL)
{
    const int d0 = blockIdx.x * 8;
    const int b  = blockIdx.y;
    extern __shared__ float sm[];
    float*  w_s = sm;
    float2* in2 = (float2*)(sm + 63*16);
    __shared__ float alpha_s[128];
    const int tid = threadIdx.x;
    if (tid < 128) alpha_s[tid] = alpha[(tid >> 3)*128 + d0 + (tid & 7)];

    const int og = tid >> 7, pos = tid & 127;
    const int cpos = pos < HW ? pos : HW-1;
    const int h = cpos / 11, w = cpos - h*11;
    const int ppc = (h+1)*13 + (w+1);

    u64 acc[4][8];
    #pragma unroll
    for (int r = 0; r < 4; r++)
        #pragma unroll
        for (int o = 0; o < 8; o++) acc[r][o] = 0ULL;

    for (int t = tid; t < OCH*63; t += 256) { int o = t/63, r = t - o*63; w_s[r*16 + o] = wt[o*63 + r]; }
    for (int t = tid; t < 13*169; t += 256) {
        int dd = t/169, pp = t - dd*169;
        int h13 = pp/13, w13 = pp - h13*13, gd = d0 - 3 + dd;
        float v0 = 0.f, v1 = 0.f;
        if (h13 >= 1 && h13 <= 11 && w13 >= 1 && w13 <= 11) {
            const float* src = in + (size_t)b*DPT*HW + (h13-1)*11 + (w13-1);
            if (gd   >= 0 && gd   < DPT) v0 = src[(size_t)gd*HW];
            if (gd+1 >= 0 && gd+1 < DPT) v1 = src[(size_t)(gd+1)*HW];
        }
        in2[t] = make_float2(v0, v1);
    }
    __syncthreads();

    const u64*   col = (const u64*)in2 + ppc;
    const float* wb  = w_s + og*8;
    #pragma unroll 1
    for (int kd = 0; kd < 7; ++kd) {
        #pragma unroll
        for (int khw = 0; khw < 9; ++khw) {
            const int kh = khw/3, kw = khw - kh*3;
            const int off = (kh-1)*13 + (kw-1);
            const float* wk = wb + (kd*9 + khw)*16;
            float4 wa = *reinterpret_cast<const float4*>(wk);
            float4 wc = *reinterpret_cast<const float4*>(wk + 4);
            u64 wd[8] = {dup2(wa.x), dup2(wa.y), dup2(wa.z), dup2(wa.w),
                         dup2(wc.x), dup2(wc.y), dup2(wc.z), dup2(wc.w)};
            #pragma unroll
            for (int r = 0; r < 4; ++r) {
                u64 a = col[(kd + 2*r)*169 + off];
                #pragma unroll
                for (int o = 0; o < 8; ++o) acc[r][o] = fma2(a, wd[o], acc[r][o]);
            }
        }
    }

    if (pos < HW) {
        #pragma unroll
        for (int o = 0; o < 8; ++o) {
            const int oc = og*8 + o;
            const float bv = bias[oc];
            float* ob = out + ((size_t)(b*OCH + oc)*DPT + d0)*HW + pos;
            float fs = 0.f;
            #pragma unroll
            for (int r = 0; r < 4; ++r) {
                F2U a; a.u = acc[r][o];
                float v0 = fmaxf(a.f.x + bv, 0.f), v1 = fmaxf(a.f.y + bv, 0.f);
                ob[(2*r  )*HW] = v0;
                ob[(2*r+1)*HW] = v1;
                fs += alpha_s[oc*8 + 2*r]*v0 + alpha_s[oc*8 + 2*r + 1]*v1;
            }
            atomicAdd(&featL[b*FEAT_SZ + oc*HW + pos], fs);
        }
    }
}

// ---------------------------------------------------------------------------
// Layers 2/3: HMMA, merged single-kk-loop 3-product passes:
// per kk: load A_hi, A_lo (4 LDS.64); per tile: load B_hi, B_lo (2 LDS.64),
// mma(acc,Ahi,Bhi), mma(acc,Alo,Bhi), mma(acc,Ahi,Blo). Drops W2X2 (~2^-16).
// Epilogue: per-thread values are unique (dl,o,p) -> plain STS into smem
// buffer [8][16][121], then 1936 global atomics per CTA (was 16K).
// ---------------------------------------------------------------------------
#define DEPS   5408
#define XSPL   75712
#define WOFFB  151424
#define WSPLB  32256
#define SMEM_CT (WOFFB + 2*WSPLB)

template<bool WRITE_SA>
__global__ void __launch_bounds__(512, 1) convT2_kernel(
    const float* __restrict__ in, const u32* __restrict__ wsp,
    const float* __restrict__ bias, float* __restrict__ out,
    const float* __restrict__ alpha, float* __restrict__ featL)
{
    extern __shared__ char smx[];
    const int d0 = blockIdx.x * 8;
    const int b  = blockIdx.y;
    const int tid = threadIdx.x, wid = tid >> 5, l = tid & 31;

    {
        u32* wdst = (u32*)(smx + WOFFB);
        for (int t = tid; t < 16128; t += 512) wdst[t] = wsp[t];
    }
    for (int t = tid; t < 8*14*169; t += 512) {
        int iq  = t / (14*169);
        int r   = t - iq*(14*169);
        int dep = r / 169, pp = r - dep*169;
        int q = iq >> 1, half = iq & 1;
        int gd  = d0 - 3 + dep;
        int h13 = pp / 13, w13 = pp - h13*13;
        float x0 = 0.f, x1 = 0.f;
        if (gd >= 0 && gd < DPT && h13 >= 1 && h13 <= 11 && w13 >= 1 && w13 <= 11) {
            int c0 = 2*q + 8*half;
            const float* src = in + ((size_t)(b*OCH + c0)*DPT + gd)*HW + (h13-1)*11 + (w13-1);
            x0 = src[0];
            x1 = src[(size_t)DPT*HW];
        }
        __nv_bfloat16 h0 = __float2bfloat16(x0);
        __nv_bfloat16 h1 = __float2bfloat16(x1);
        __nv_bfloat16 l0 = __float2bfloat16(x0 - __bfloat162float(h0));
        __nv_bfloat16 l1 = __float2bfloat16(x1 - __bfloat162float(h1));
        int addr = dep*DEPS + pp*32 + q*8 + half*4;
        *(u32*)(smx + addr)        = pack_bf16(h0, h1);
        *(u32*)(smx + XSPL + addr) = pack_bf16(l0, l1);
    }
    __syncthreads();

    int coff[8];
    #pragma unroll
    for (int k = 0; k < 8; ++k) {
        int T = wid + 16*k;
        int Tc = T < 121 ? T : 120;
        int n  = Tc*8 + (l >> 2);
        int dl = n / 121, p = n - dl*121;
        int pp = (p/11 + 1)*13 + (p%11) + 1;
        coff[k] = dl*DEPS + pp*32 + (l & 3)*8;
    }
    const int aoff = (l >> 2)*32 + (l & 3)*8;

    float acc[8][4];
    #pragma unroll
    for (int k = 0; k < 8; ++k)
        #pragma unroll
        for (int q = 0; q < 4; ++q) acc[k][q] = 0.f;

    const bool last_ok = (wid < 9);
    #pragma unroll 1
    for (int kk = 0; kk < 63; ++kk) {
        const char* Wk = smx + WOFFB + kk*512;
        u64 h02 = *(const u64*)(Wk + aoff);
        u64 h13v = *(const u64*)(Wk + aoff + 256);
        u64 l02 = *(const u64*)(Wk + WSPLB + aoff);
        u64 l13v = *(const u64*)(Wk + WSPLB + aoff + 256);
        u32 ah0 = (u32)h02, ah2 = (u32)(h02 >> 32);
        u32 ah1 = (u32)h13v, ah3 = (u32)(h13v >> 32);
        u32 al0 = (u32)l02, al2 = (u32)(l02 >> 32);
        u32 al1 = (u32)l13v, al3 = (u32)(l13v >> 32);
        int kd = kk / 9, khw = kk - kd*9;
        int kh = khw / 3, kw = khw - kh*3;
        const char* Xk = smx + kd*DEPS + ((kh-1)*13 + (kw-1))*32;
        #pragma unroll
        for (int k = 0; k < 8; ++k) {
            if (k < 7 || last_ok) {
                u64 bh = *(const u64*)(Xk + coff[k]);
                u64 bl = *(const u64*)(Xk + XSPL + coff[k]);
                mma_bf16(acc[k], ah0, ah1, ah2, ah3, (u32)bh, (u32)(bh >> 32));
                mma_bf16(acc[k], al0, al1, al2, al3, (u32)bh, (u32)(bh >> 32));
                mma_bf16(acc[k], ah0, ah1, ah2, ah3, (u32)bl, (u32)(bl >> 32));
            }
        }
    }

    __syncthreads();   // mma done; reuse X slab as pbuf[8 dl][16 o][121 p]
    float* pbuf = (float*)smx;

    const int o0 = l >> 2, o1 = o0 + 8;
    const float bv0 = bias[o0], bv1 = bias[o1];
    #pragma unroll 1
    for (int k = 0; k < 8; ++k) {
        if (k < 7 || last_ok) {
            int T = wid + 16*k;
            #pragma unroll
            for (int cc = 0; cc < 2; ++cc) {
                int nn = T*8 + (l & 3)*2 + cc;
                int dl = nn / 121, p = nn - dl*121;
                int gdo = d0 + dl;
                float v0 = fmaxf(acc[k][cc    ] + bv0, 0.f);
                float v1 = fmaxf(acc[k][cc + 2] + bv1, 0.f);
                if (WRITE_SA) {
                    out[((size_t)(b*OCH + o0)*DPT + gdo)*HW + p] = v0;
                    out[((size_t)(b*OCH + o1)*DPT + gdo)*HW + p] = v1;
                }
                pbuf[(dl*16 + o0)*121 + p] = alpha[o0*128 + gdo]*v0;
                pbuf[(dl*16 + o1)*121 + p] = alpha[o1*128 + gdo]*v1;
            }
        }
    }
    __syncthreads();
    for (int t = tid; t < FEAT_SZ; t += 512) {
        int o = t / 121, p = t - o*121;
        float s = 0.f;
        #pragma unroll
        for (int dl = 0; dl < 8; ++dl) s += pbuf[(dl*16 + o)*121 + p];
        atomicAdd(&featL[b*FEAT_SZ + t], s);
    }
}

// ---------------------------------------------------------------------------
__global__ void relu_kernel(float* x, int n)
{
    int t = blockIdx.x*blockDim.x + threadIdx.x;
    if (t < n) x[t] = fmaxf(x[t], 0.f);
}

__global__ void conv45_kernel(const float* __restrict__ feat2,
                              const float* __restrict__ w45, const float* __restrict__ b45,
                              float* __restrict__ feat3, float* __restrict__ feat4)
{
    const int b = blockIdx.x, tid = threadIdx.x;
    __shared__ float fa[FEAT_SZ], fb[FEAT_SZ];
    for (int t = tid; t < FEAT_SZ; t += 128) fa[t] = feat2[b*FEAT_SZ + t];
    __syncthreads();
    if (tid < HW) {
        int h = tid / 11, w = tid - h*11;
        for (int o = 0; o < 16; o++) {
            float acc = b45[o];
            for (int c = 0; c < 16; c++)
                for (int kh = 0; kh < 3; kh++) {
                    int hh = h + kh - 1; if (hh < 0 || hh >= 11) continue;
                    for (int kw = 0; kw < 3; kw++) {
                        int ww2 = w + kw - 1; if (ww2 < 0 || ww2 >= 11) continue;
                        acc += fa[c*HW + hh*11 + ww2] * w45[(o*16 + c)*9 + kh*3 + kw];
                    }
                }
            float v = fmaxf(acc, 0.f);
            fb[o*HW + tid] = v;
            feat3[b*FEAT_SZ + o*HW + tid] = v;
        }
    }
    __syncthreads();
    if (tid < HW) {
        int h = tid / 11, w = tid - h*11;
        for (int o = 0; o < 16; o++) {
            float acc = b45[16 + o];
            for (int c = 0; c < 16; c++)
                for (int kh = 0; kh < 3; kh++) {
                    int hh = h + kh - 1; if (hh < 0 || hh >= 11) continue;
                    for (int kw = 0; kw < 3; kw++) {
                        int ww2 = w + kw - 1; if (ww2 < 0 || ww2 >= 11) continue;
                        acc += fb[c*HW + hh*11 + ww2] * w45[2304 + (o*16 + c)*9 + kh*3 + kw];
                    }
                }
            feat4[b*FEAT_SZ + o*HW + tid] = fmaxf(acc, 0.f);
        }
    }
}

__global__ void side_kernel(const float* __restrict__ x, const float* __restrict__ feat,
    const float* __restrict__ sw,  const float* __restrict__ sb,
    const float* __restrict__ sow, const float* __restrict__ sob,
    const float* __restrict__ wa,  const float* __restrict__ ba,
    const float* __restrict__ wb,  const float* __restrict__ bbv,
    const float* __restrict__ ssw, const float* __restrict__ ssb,
    const float* __restrict__ fuse, float* __restrict__ out)
{
    const int i = blockIdx.x, b = blockIdx.y, tid = threadIdx.x;
    __shared__ float f_s[FEAT_SZ], act_s[HW], diff_s[HW], s_arr[128], xc[128], y1_s[144], y2_s[16];
    __shared__ int idx_s[5];

    for (int t = tid; t < FEAT_SZ; t += 128)
        f_s[t] = feat[i*(BB*FEAT_SZ) + b*FEAT_SZ + t];
    __syncthreads();

    if (tid < HW) {
        int h = tid / 11, w = tid - h*11;
        float acc = sb[i];
        for (int c = 0; c < 16; c++)
            for (int kh = 0; kh < 3; kh++) {
                int hh = h + kh - 1; if (hh < 0 || hh >= 11) continue;
                for (int kw = 0; kw < 3; kw++) {
                    int ww2 = w + kw - 1; if (ww2 < 0 || ww2 >= 11) continue;
                    acc += f_s[c*HW + hh*11 + ww2] * sw[(i*16 + c)*9 + kh*3 + kw];
                }
            }
        act_s[tid] = acc;
    }
    __syncthreads();
    if (tid < HW) diff_s[tid] = fabsf(act_s[tid] - act_s[60]);
    __syncthreads();
    if (tid == 0) {
        for (int j = 0; j < 5; j++) {
            float best = 3.4e38f; int bi = 0;
            for (int p = 0; p < HW; p++) { float d = diff_s[p]; if (d < best) { best = d; bi = p; } }
            idx_s[j] = bi; diff_s[bi] = 3.4e38f;
        }
    }
    __syncthreads();
    {
        float s = 0.f;
        const float* xb = x + (size_t)(b*128 + tid)*HW;
        #pragma unroll
        for (int j = 0; j < 5; j++) s += xb[idx_s[j]];
        s_arr[tid] = s;
        xc[tid] = xb[60];
    }
    __syncthreads();
    for (int t = tid; t < 144; t += 128) {
        int o = t / 9, j = t - o*9;
        int pj = 62 + 2*(j/3), qj = 62 + 2*(j%3);
        float acc = ba[i*16 + o];
        #pragma unroll
        for (int ch = 0; ch < 2; ch++) {
            const float* num = ch ? xc : s_arr;
            #pragma unroll
            for (int eh = 0; eh < 3; eh++)
                #pragma unroll
                for (int ew = 0; ew < 3; ew++) {
                    int r = pj + eh - 1, c = qj + ew - 1;
                    float den = num[c];
                    den = fabsf(den) < 0.01f ? 0.01f : den;
                    acc += (num[r] / den) * wa[(((i*16 + o)*2 + ch)*3 + eh)*3 + ew];
                }
        }
        y1_s[o*9 + j] = fmaxf(acc, 0.f);
    }
    __syncthreads();
    if (tid < 16) {
        float acc = bbv[i*16 + tid];
        for (int c = 0; c < 16; c++)
            #pragma unroll
            for (int j = 0; j < 9; j++)
                acc += y1_s[c*9 + j] * wb[((i*16 + tid)*16 + c)*9 + j];
        y2_s[tid] = fmaxf(acc, 0.f);
    }
    __syncthreads();
    if (tid < 16) {
        float sa_v = sob[i*16 + tid];
        for (int k = 0; k < 16; k++) sa_v += f_s[k*HW + 60] * sow[(i*16 + tid)*16 + k];
        float sp_v = ssb[i*16 + tid];
        for (int c = 0; c < 16; c++) sp_v += y2_s[c] * ssw[(i*16 + tid)*16 + c];
        atomicAdd(&out[b*16 + tid], fuse[i]*sa_v + fuse[5 + i]*sp_v);
    }
}

// ---------------------------------------------------------------------------
extern "C" void kernel_launch(void* const* d_in, const int* in_sizes, int n_in,
                              void* d_out, int out_size)
{
    const float* x      = (const float*)d_in[0];
    const float* w3d1   = (const float*)d_in[1];
    const float* b3d1   = (const float*)d_in[2];
    const float* w3d23  = (const float*)d_in[3];
    const float* b3d23  = (const float*)d_in[4];
    const float* cpr_w  = (const float*)d_in[5];
    const float* w2d45  = (const float*)d_in[6];
    const float* b2d45  = (const float*)d_in[7];
    const float* seg_w  = (const float*)d_in[8];
    const float* seg_b  = (const float*)d_in[9];
    const float* so_w   = (const float*)d_in[10];
    const float* so_b   = (const float*)d_in[11];
    const float* sp_wa  = (const float*)d_in[12];
    const float* sp_ba  = (const float*)d_in[13];
    const float* sp_wb  = (const float*)d_in[14];
    const float* sp_bb  = (const float*)d_in[15];
    const float* sp_sw  = (const float*)d_in[16];
    const float* sp_sb  = (const float*)d_in[17];
    const float* fuse   = (const float*)d_in[18];
    float* out = (float*)d_out;

    float *sa1, *sa2, *feat, *alpha;
    u32* wsp;
    cudaGetSymbolAddress((void**)&sa1,   g_sa1);
    cudaGetSymbolAddress((void**)&sa2,   g_sa2);
    cudaGetSymbolAddress((void**)&feat,  g_feat);
    cudaGetSymbolAddress((void**)&alpha, g_alpha);
    cudaGetSymbolAddress((void**)&wsp,   g_wsplit);

    const int SMEM1 = 63*16*4 + 13*169*8;
    cudaFuncSetAttribute((const void*)conv3d1_kernel, cudaFuncAttributeMaxDynamicSharedMemorySize, SMEM1);
    cudaFuncSetAttribute((const void*)convT2_kernel<true>,  cudaFuncAttributeMaxDynamicSharedMemorySize, SMEM_CT);
    cudaFuncSetAttribute((const void*)convT2_kernel<false>, cudaFuncAttributeMaxDynamicSharedMemorySize, SMEM_CT);

    const int prep_blocks = 116 + (3*BB*FEAT_SZ + 255)/256;
    prep_kernel<<<prep_blocks, 256>>>(cpr_w, w3d23, alpha, wsp, out, out_size, feat);

    conv3d1_kernel<<<dim3(16, BB), 256, SMEM1>>>(
        x, w3d1, b3d1, sa1, alpha + 0*2048, feat + 0*(BB*FEAT_SZ));

    convT2_kernel<true><<<dim3(16, BB), 512, SMEM_CT>>>(
        sa1, wsp, b3d23, sa2, alpha + 1*2048, feat + 1*(BB*FEAT_SZ));

    convT2_kernel<false><<<dim3(16, BB), 512, SMEM_CT>>>(
        sa2, wsp + 16128, b3d23 + 16, sa1 /*unused*/, alpha + 2*2048, feat + 2*(BB*FEAT_SZ));

    relu_kernel<<<(3*BB*FEAT_SZ + 255)/256, 256>>>(feat, 3*BB*FEAT_SZ);

    conv45_kernel<<<BB, 128>>>(feat + 2*(BB*FEAT_SZ), w2d45, b2d45,
                               feat + 3*(BB*FEAT_SZ), feat + 4*(BB*FEAT_SZ));

    side_kernel<<<dim3(5, BB), 128>>>(x, feat, seg_w, seg_b, so_w, so_b,
                                      sp_wa, sp_ba, sp_wb, sp_bb, sp_sw, sp_sb,
                                      fuse, out);
}

// round 16
// speedup vs baseline: 5.0637x; 1.2109x over previous
#include <cuda_runtime.h>
#include <cuda_bf16.h>

#define BB   64
#define DPT  128
#define HW   121
#define OCH  16
#define FEAT_SZ (OCH*HW)

typedef unsigned long long u64;
typedef unsigned int u32;
union F2U { u64 u; float2 f; };

__device__ __forceinline__ u64 fma2(u64 a, u64 b, u64 c) {
    u64 d; asm("fma.rn.f32x2 %0, %1, %2, %3;" : "=l"(d) : "l"(a), "l"(b), "l"(c)); return d;
}
__device__ __forceinline__ u64 dup2(float w) {
    u64 d; asm("mov.b64 %0, {%1, %1};" : "=l"(d) : "f"(w)); return d;
}
__device__ __forceinline__ void mma_bf16(float (&c)[4], u32 a0, u32 a1, u32 a2, u32 a3,
                                         u32 b0, u32 b1) {
    asm volatile("mma.sync.aligned.m16n8k16.row.col.f32.bf16.bf16.f32 "
        "{%0,%1,%2,%3}, {%4,%5,%6,%7}, {%8,%9}, {%0,%1,%2,%3};"
        : "+f"(c[0]), "+f"(c[1]), "+f"(c[2]), "+f"(c[3])
        : "r"(a0), "r"(a1), "r"(a2), "r"(a3), "r"(b0), "r"(b1));
}
__device__ __forceinline__ u32 pack_bf16(__nv_bfloat16 lo, __nv_bfloat16 hi) {
    __nv_bfloat162 t = __nv_bfloat162(lo, hi);
    return *reinterpret_cast<u32*>(&t);
}

__device__ float g_sa1[BB*OCH*DPT*HW];
__device__ float g_sa2[BB*OCH*DPT*HW];
__device__ float g_feat[5*BB*OCH*HW];
__device__ float g_alpha[3*OCH*DPT];
__device__ u32   g_wsplit[2*16128];

// ---------------------------------------------------------------------------
// prep: alpha softmax (blocks 0..47), weight split (48..111), zero out/feat.
// ---------------------------------------------------------------------------
__global__ void prep_kernel(const float* __restrict__ cw, const float* __restrict__ w3d23,
                            float* __restrict__ alpha, u32* __restrict__ wsp,
                            float* __restrict__ out, int out_n, float* __restrict__ feat)
{
    const int bid = blockIdx.x, tid = threadIdx.x;
    if (bid < 48) {
        __shared__ float red[128];
        float wv = 0.f, e = 0.f;
        if (tid < 128) { wv = cw[bid*128 + tid]; red[tid] = wv; }
        __syncthreads();
        for (int s = 64; s > 0; s >>= 1) { if (tid < s) red[tid] = fmaxf(red[tid], red[tid+s]); __syncthreads(); }
        float mx = red[0]; __syncthreads();
        if (tid < 128) { e = expf(wv - mx); red[tid] = e; }
        __syncthreads();
        for (int s = 64; s > 0; s >>= 1) { if (tid < s) red[tid] += red[tid+s]; __syncthreads(); }
        if (tid < 128) alpha[bid*128 + tid] = e / red[0];
    } else if (bid < 112) {
        int g = (bid - 48)*256 + tid;
        if (g < 16128) {
            int layer = g / 8064, tt = g - layer*8064;
            int kk = tt >> 7, r = tt & 127;
            int o = r >> 3, s2 = r & 7;
            int q = s2 >> 1, half = s2 & 1;
            const float* wt = w3d23 + layer*16128;
            int c0 = 2*q + 8*half;
            float x0 = wt[o*1008 + c0*63 + kk];
            float x1 = wt[o*1008 + (c0+1)*63 + kk];
            __nv_bfloat16 h0 = __float2bfloat16(x0);
            __nv_bfloat16 h1 = __float2bfloat16(x1);
            __nv_bfloat16 l0 = __float2bfloat16(x0 - __bfloat162float(h0));
            __nv_bfloat16 l1 = __float2bfloat16(x1 - __bfloat162float(h1));
            u32* dst = wsp + layer*16128;
            dst[tt]        = pack_bf16(h0, h1);
            dst[8064 + tt] = pack_bf16(l0, l1);
        }
    } else if (bid < 116) {
        int g = (bid - 112)*256 + tid;
        if (g < out_n) out[g] = 0.f;
    } else {
        int g = (bid - 116)*256 + tid;
        if (g < 3*BB*FEAT_SZ) feat[g] = 0.f;
    }
}

// ---------------------------------------------------------------------------
// Layer-1 scalar conv (ICH=1), packed f32x2, fused cpr partials
// ---------------------------------------------------------------------------
__global__ void __launch_bounds__(256, 2) conv3d1_kernel(
    const float* __restrict__ in, const float* __restrict__ wt,
    const float* __restrict__ bias, float* __restrict__ out,
    const float* __restrict__ alpha, float* __restrict__ featL)
{
    const int d0 = blockIdx.x * 8;
    const int b  = blockIdx.y;
    extern __shared__ float sm[];
    float*  w_s = sm;
    float2* in2 = (float2*)(sm + 63*16);
    __shared__ float alpha_s[128];
    const int tid = threadIdx.x;
    if (tid < 128) alpha_s[tid] = alpha[(tid >> 3)*128 + d0 + (tid & 7)];

    const int og = tid >> 7, pos = tid & 127;
    const int cpos = pos < HW ? pos : HW-1;
    const int h = cpos / 11, w = cpos - h*11;
    const int ppc = (h+1)*13 + (w+1);

    u64 acc[4][8];
    #pragma unroll
    for (int r = 0; r < 4; r++)
        #pragma unroll
        for (int o = 0; o < 8; o++) acc[r][o] = 0ULL;

    for (int t = tid; t < OCH*63; t += 256) { int o = t/63, r = t - o*63; w_s[r*16 + o] = wt[o*63 + r]; }
    for (int t = tid; t < 13*169; t += 256) {
        int dd = t/169, pp = t - dd*169;
        int h13 = pp/13, w13 = pp - h13*13, gd = d0 - 3 + dd;
        float v0 = 0.f, v1 = 0.f;
        if (h13 >= 1 && h13 <= 11 && w13 >= 1 && w13 <= 11) {
            const float* src = in + (size_t)b*DPT*HW + (h13-1)*11 + (w13-1);
            if (gd   >= 0 && gd   < DPT) v0 = src[(size_t)gd*HW];
            if (gd+1 >= 0 && gd+1 < DPT) v1 = src[(size_t)(gd+1)*HW];
        }
        in2[t] = make_float2(v0, v1);
    }
    __syncthreads();

    const u64*   col = (const u64*)in2 + ppc;
    const float* wb  = w_s + og*8;
    #pragma unroll 1
    for (int kd = 0; kd < 7; ++kd) {
        #pragma unroll
        for (int khw = 0; khw < 9; ++khw) {
            const int kh = khw/3, kw = khw - kh*3;
            const int off = (kh-1)*13 + (kw-1);
            const float* wk = wb + (kd*9 + khw)*16;
            float4 wa = *reinterpret_cast<const float4*>(wk);
            float4 wc = *reinterpret_cast<const float4*>(wk + 4);
            u64 wd[8] = {dup2(wa.x), dup2(wa.y), dup2(wa.z), dup2(wa.w),
                         dup2(wc.x), dup2(wc.y), dup2(wc.z), dup2(wc.w)};
            #pragma unroll
            for (int r = 0; r < 4; ++r) {
                u64 a = col[(kd + 2*r)*169 + off];
                #pragma unroll
                for (int o = 0; o < 8; ++o) acc[r][o] = fma2(a, wd[o], acc[r][o]);
            }
        }
    }

    if (pos < HW) {
        #pragma unroll
        for (int o = 0; o < 8; ++o) {
            const int oc = og*8 + o;
            const float bv = bias[oc];
            float* ob = out + ((size_t)(b*OCH + oc)*DPT + d0)*HW + pos;
            float fs = 0.f;
            #pragma unroll
            for (int r = 0; r < 4; ++r) {
                F2U a; a.u = acc[r][o];
                float v0 = fmaxf(a.f.x + bv, 0.f), v1 = fmaxf(a.f.y + bv, 0.f);
                ob[(2*r  )*HW] = v0;
                ob[(2*r+1)*HW] = v1;
                fs += alpha_s[oc*8 + 2*r]*v0 + alpha_s[oc*8 + 2*r + 1]*v1;
            }
            atomicAdd(&featL[b*FEAT_SZ + oc*HW + pos], fs);
        }
    }
}

// ---------------------------------------------------------------------------
// Layers 2/3: HMMA, merged 3-product kk loop, BATCHED B loads (all 16
// fragments into registers before the 24 mmas -> LDS latency hidden in-iter).
// Epilogue: smem partial buffer + 1936 atomics per CTA.
// ---------------------------------------------------------------------------
#define DEPS   5408
#define XSPL   75712
#define WOFFB  151424
#define WSPLB  32256
#define SMEM_CT (WOFFB + 2*WSPLB)

template<bool WRITE_SA>
__global__ void __launch_bounds__(512, 1) convT2_kernel(
    const float* __restrict__ in, const u32* __restrict__ wsp,
    const float* __restrict__ bias, float* __restrict__ out,
    const float* __restrict__ alpha, float* __restrict__ featL)
{
    extern __shared__ char smx[];
    const int d0 = blockIdx.x * 8;
    const int b  = blockIdx.y;
    const int tid = threadIdx.x, wid = tid >> 5, l = tid & 31;

    {
        u32* wdst = (u32*)(smx + WOFFB);
        for (int t = tid; t < 16128; t += 512) wdst[t] = wsp[t];
    }
    for (int t = tid; t < 8*14*169; t += 512) {
        int iq  = t / (14*169);
        int r   = t - iq*(14*169);
        int dep = r / 169, pp = r - dep*169;
        int q = iq >> 1, half = iq & 1;
        int gd  = d0 - 3 + dep;
        int h13 = pp / 13, w13 = pp - h13*13;
        float x0 = 0.f, x1 = 0.f;
        if (gd >= 0 && gd < DPT && h13 >= 1 && h13 <= 11 && w13 >= 1 && w13 <= 11) {
            int c0 = 2*q + 8*half;
            const float* src = in + ((size_t)(b*OCH + c0)*DPT + gd)*HW + (h13-1)*11 + (w13-1);
            x0 = src[0];
            x1 = src[(size_t)DPT*HW];
        }
        __nv_bfloat16 h0 = __float2bfloat16(x0);
        __nv_bfloat16 h1 = __float2bfloat16(x1);
        __nv_bfloat16 l0 = __float2bfloat16(x0 - __bfloat162float(h0));
        __nv_bfloat16 l1 = __float2bfloat16(x1 - __bfloat162float(h1));
        int addr = dep*DEPS + pp*32 + q*8 + half*4;
        *(u32*)(smx + addr)        = pack_bf16(h0, h1);
        *(u32*)(smx + XSPL + addr) = pack_bf16(l0, l1);
    }
    __syncthreads();

    int coff[8];
    #pragma unroll
    for (int k = 0; k < 8; ++k) {
        int T = wid + 16*k;
        int Tc = T < 121 ? T : 120;
        int n  = Tc*8 + (l >> 2);
        int dl = n / 121, p = n - dl*121;
        int pp = (p/11 + 1)*13 + (p%11) + 1;
        coff[k] = dl*DEPS + pp*32 + (l & 3)*8;
    }
    const int aoff = (l >> 2)*32 + (l & 3)*8;

    float acc[8][4];
    #pragma unroll
    for (int k = 0; k < 8; ++k)
        #pragma unroll
        for (int q = 0; q < 4; ++q) acc[k][q] = 0.f;

    const bool last_ok = (wid < 9);
    #pragma unroll 1
    for (int kk = 0; kk < 63; ++kk) {
        const char* Wk = smx + WOFFB + kk*512;
        u64 h02 = *(const u64*)(Wk + aoff);
        u64 h13v = *(const u64*)(Wk + aoff + 256);
        u64 l02 = *(const u64*)(Wk + WSPLB + aoff);
        u64 l13v = *(const u64*)(Wk + WSPLB + aoff + 256);
        u32 ah0 = (u32)h02, ah2 = (u32)(h02 >> 32);
        u32 ah1 = (u32)h13v, ah3 = (u32)(h13v >> 32);
        u32 al0 = (u32)l02, al2 = (u32)(l02 >> 32);
        u32 al1 = (u32)l13v, al3 = (u32)(l13v >> 32);
        int kd = kk / 9, khw = kk - kd*9;
        int kh = khw / 3, kw = khw - kh*3;
        const char* Xk = smx + kd*DEPS + ((kh-1)*13 + (kw-1))*32;
        // batch ALL B loads first (latency hiding), then all mmas
        u64 bh[8], bl[8];
        #pragma unroll
        for (int k = 0; k < 8; ++k) {
            if (k < 7 || last_ok) {
                bh[k] = *(const u64*)(Xk + coff[k]);
                bl[k] = *(const u64*)(Xk + XSPL + coff[k]);
            }
        }
        #pragma unroll
        for (int k = 0; k < 8; ++k) {
            if (k < 7 || last_ok) {
                mma_bf16(acc[k], ah0, ah1, ah2, ah3, (u32)bh[k], (u32)(bh[k] >> 32));
                mma_bf16(acc[k], al0, al1, al2, al3, (u32)bh[k], (u32)(bh[k] >> 32));
                mma_bf16(acc[k], ah0, ah1, ah2, ah3, (u32)bl[k], (u32)(bl[k] >> 32));
            }
        }
    }

    __syncthreads();   // mma done; reuse X slab as pbuf[8 dl][16 o][121 p]
    float* pbuf = (float*)smx;

    const int o0 = l >> 2, o1 = o0 + 8;
    const float bv0 = bias[o0], bv1 = bias[o1];
    #pragma unroll 1
    for (int k = 0; k < 8; ++k) {
        if (k < 7 || last_ok) {
            int T = wid + 16*k;
            #pragma unroll
            for (int cc = 0; cc < 2; ++cc) {
                int nn = T*8 + (l & 3)*2 + cc;
                int dl = nn / 121, p = nn - dl*121;
                int gdo = d0 + dl;
                float v0 = fmaxf(acc[k][cc    ] + bv0, 0.f);
                float v1 = fmaxf(acc[k][cc + 2] + bv1, 0.f);
                if (WRITE_SA) {
                    out[((size_t)(b*OCH + o0)*DPT + gdo)*HW + p] = v0;
                    out[((size_t)(b*OCH + o1)*DPT + gdo)*HW + p] = v1;
                }
                pbuf[(dl*16 + o0)*121 + p] = alpha[o0*128 + gdo]*v0;
                pbuf[(dl*16 + o1)*121 + p] = alpha[o1*128 + gdo]*v1;
            }
        }
    }
    __syncthreads();
    for (int t = tid; t < FEAT_SZ; t += 512) {
        int o = t / 121, p = t - o*121;
        float s = 0.f;
        #pragma unroll
        for (int dl = 0; dl < 8; ++dl) s += pbuf[(dl*16 + o)*121 + p];
        atomicAdd(&featL[b*FEAT_SZ + t], s);
    }
}

// ---------------------------------------------------------------------------
__global__ void relu_kernel(float* x, int n)
{
    int t = blockIdx.x*blockDim.x + threadIdx.x;
    if (t < n) x[t] = fmaxf(x[t], 0.f);
}

// conv4/conv5 2D, 512 threads: og = tid>>7 handles 4 o each, pos = tid&127.
__global__ void __launch_bounds__(512) conv45_kernel(
    const float* __restrict__ feat2,
    const float* __restrict__ w45, const float* __restrict__ b45,
    float* __restrict__ feat3, float* __restrict__ feat4)
{
    const int b = blockIdx.x, tid = threadIdx.x;
    const int og = tid >> 7, pos = tid & 127;
    __shared__ float fa[FEAT_SZ], fb[FEAT_SZ];
    for (int t = tid; t < FEAT_SZ; t += 512) fa[t] = feat2[b*FEAT_SZ + t];
    __syncthreads();
    if (pos < HW) {
        int h = pos / 11, w = pos - h*11;
        for (int oo = 0; oo < 4; oo++) {
            int o = og*4 + oo;
            float acc = b45[o];
            for (int c = 0; c < 16; c++)
                #pragma unroll
                for (int kh = 0; kh < 3; kh++) {
                    int hh = h + kh - 1; if (hh < 0 || hh >= 11) continue;
                    #pragma unroll
                    for (int kw = 0; kw < 3; kw++) {
                        int ww2 = w + kw - 1; if (ww2 < 0 || ww2 >= 11) continue;
                        acc += fa[c*HW + hh*11 + ww2] * w45[(o*16 + c)*9 + kh*3 + kw];
                    }
                }
            float v = fmaxf(acc, 0.f);
            fb[o*HW + pos] = v;
            feat3[b*FEAT_SZ + o*HW + pos] = v;
        }
    }
    __syncthreads();
    if (pos < HW) {
        int h = pos / 11, w = pos - h*11;
        for (int oo = 0; oo < 4; oo++) {
            int o = og*4 + oo;
            float acc = b45[16 + o];
            for (int c = 0; c < 16; c++)
                #pragma unroll
                for (int kh = 0; kh < 3; kh++) {
                    int hh = h + kh - 1; if (hh < 0 || hh >= 11) continue;
                    #pragma unroll
                    for (int kw = 0; kw < 3; kw++) {
                        int ww2 = w + kw - 1; if (ww2 < 0 || ww2 >= 11) continue;
                        acc += fb[c*HW + hh*11 + ww2] * w45[2304 + (o*16 + c)*9 + kh*3 + kw];
                    }
                }
            feat4[b*FEAT_SZ + o*HW + pos] = fmaxf(acc, 0.f);
        }
    }
}

__global__ void side_kernel(const float* __restrict__ x, const float* __restrict__ feat,
    const float* __restrict__ sw,  const float* __restrict__ sb,
    const float* __restrict__ sow, const float* __restrict__ sob,
    const float* __restrict__ wa,  const float* __restrict__ ba,
    const float* __restrict__ wb,  const float* __restrict__ bbv,
    const float* __restrict__ ssw, const float* __restrict__ ssb,
    const float* __restrict__ fuse, float* __restrict__ out)
{
    const int i = blockIdx.x, b = blockIdx.y, tid = threadIdx.x;
    __shared__ float f_s[FEAT_SZ], act_s[HW], diff_s[HW], s_arr[128], xc[128], y1_s[144], y2_s[16];
    __shared__ int idx_s[5];

    for (int t = tid; t < FEAT_SZ; t += 128)
        f_s[t] = feat[i*(BB*FEAT_SZ) + b*FEAT_SZ + t];
    __syncthreads();

    if (tid < HW) {
        int h = tid / 11, w = tid - h*11;
        float acc = sb[i];
        for (int c = 0; c < 16; c++)
            for (int kh = 0; kh < 3; kh++) {
                int hh = h + kh - 1; if (hh < 0 || hh >= 11) continue;
                for (int kw = 0; kw < 3; kw++) {
                    int ww2 = w + kw - 1; if (ww2 < 0 || ww2 >= 11) continue;
                    acc += f_s[c*HW + hh*11 + ww2] * sw[(i*16 + c)*9 + kh*3 + kw];
                }
            }
        act_s[tid] = acc;
    }
    __syncthreads();
    if (tid < HW) diff_s[tid] = fabsf(act_s[tid] - act_s[60]);
    __syncthreads();
    if (tid == 0) {
        for (int j = 0; j < 5; j++) {
            float best = 3.4e38f; int bi = 0;
            for (int p = 0; p < HW; p++) { float d = diff_s[p]; if (d < best) { best = d; bi = p; } }
            idx_s[j] = bi; diff_s[bi] = 3.4e38f;
        }
    }
    __syncthreads();
    {
        float s = 0.f;
        const float* xb = x + (size_t)(b*128 + tid)*HW;
        #pragma unroll
        for (int j = 0; j < 5; j++) s += xb[idx_s[j]];
        s_arr[tid] = s;
        xc[tid] = xb[60];
    }
    __syncthreads();
    for (int t = tid; t < 144; t += 128) {
        int o = t / 9, j = t - o*9;
        int pj = 62 + 2*(j/3), qj = 62 + 2*(j%3);
        float acc = ba[i*16 + o];
        #pragma unroll
        for (int ch = 0; ch < 2; ch++) {
            const float* num = ch ? xc : s_arr;
            #pragma unroll
            for (int eh = 0; eh < 3; eh++)
                #pragma unroll
                for (int ew = 0; ew < 3; ew++) {
                    int r = pj + eh - 1, c = qj + ew - 1;
                    float den = num[c];
                    den = fabsf(den) < 0.01f ? 0.01f : den;
                    acc += (num[r] / den) * wa[(((i*16 + o)*2 + ch)*3 + eh)*3 + ew];
                }
        }
        y1_s[o*9 + j] = fmaxf(acc, 0.f);
    }
    __syncthreads();
    if (tid < 16) {
        float acc = bbv[i*16 + tid];
        for (int c = 0; c < 16; c++)
            #pragma unroll
            for (int j = 0; j < 9; j++)
                acc += y1_s[c*9 + j] * wb[((i*16 + tid)*16 + c)*9 + j];
        y2_s[tid] = fmaxf(acc, 0.f);
    }
    __syncthreads();
    if (tid < 16) {
        float sa_v = sob[i*16 + tid];
        for (int k = 0; k < 16; k++) sa_v += f_s[k*HW + 60] * sow[(i*16 + tid)*16 + k];
        float sp_v = ssb[i*16 + tid];
        for (int c = 0; c < 16; c++) sp_v += y2_s[c] * ssw[(i*16 + tid)*16 + c];
        atomicAdd(&out[b*16 + tid], fuse[i]*sa_v + fuse[5 + i]*sp_v);
    }
}

// ---------------------------------------------------------------------------
extern "C" void kernel_launch(void* const* d_in, const int* in_sizes, int n_in,
                              void* d_out, int out_size)
{
    const float* x      = (const float*)d_in[0];
    const float* w3d1   = (const float*)d_in[1];
    const float* b3d1   = (const float*)d_in[2];
    const float* w3d23  = (const float*)d_in[3];
    const float* b3d23  = (const float*)d_in[4];
    const float* cpr_w  = (const float*)d_in[5];
    const float* w2d45  = (const float*)d_in[6];
    const float* b2d45  = (const float*)d_in[7];
    const float* seg_w  = (const float*)d_in[8];
    const float* seg_b  = (const float*)d_in[9];
    const float* so_w   = (const float*)d_in[10];
    const float* so_b   = (const float*)d_in[11];
    const float* sp_wa  = (const float*)d_in[12];
    const float* sp_ba  = (const float*)d_in[13];
    const float* sp_wb  = (const float*)d_in[14];
    const float* sp_bb  = (const float*)d_in[15];
    const float* sp_sw  = (const float*)d_in[16];
    const float* sp_sb  = (const float*)d_in[17];
    const float* fuse   = (const float*)d_in[18];
    float* out = (float*)d_out;

    float *sa1, *sa2, *feat, *alpha;
    u32* wsp;
    cudaGetSymbolAddress((void**)&sa1,   g_sa1);
    cudaGetSymbolAddress((void**)&sa2,   g_sa2);
    cudaGetSymbolAddress((void**)&feat,  g_feat);
    cudaGetSymbolAddress((void**)&alpha, g_alpha);
    cudaGetSymbolAddress((void**)&wsp,   g_wsplit);

    const int SMEM1 = 63*16*4 + 13*169*8;
    cudaFuncSetAttribute((const void*)conv3d1_kernel, cudaFuncAttributeMaxDynamicSharedMemorySize, SMEM1);
    cudaFuncSetAttribute((const void*)convT2_kernel<true>,  cudaFuncAttributeMaxDynamicSharedMemorySize, SMEM_CT);
    cudaFuncSetAttribute((const void*)convT2_kernel<false>, cudaFuncAttributeMaxDynamicSharedMemorySize, SMEM_CT);

    const int prep_blocks = 116 + (3*BB*FEAT_SZ + 255)/256;
    prep_kernel<<<prep_blocks, 256>>>(cpr_w, w3d23, alpha, wsp, out, out_size, feat);

    conv3d1_kernel<<<dim3(16, BB), 256, SMEM1>>>(
        x, w3d1, b3d1, sa1, alpha + 0*2048, feat + 0*(BB*FEAT_SZ));

    convT2_kernel<true><<<dim3(16, BB), 512, SMEM_CT>>>(
        sa1, wsp, b3d23, sa2, alpha + 1*2048, feat + 1*(BB*FEAT_SZ));

    convT2_kernel<false><<<dim3(16, BB), 512, SMEM_CT>>>(
        sa2, wsp + 16128, b3d23 + 16, sa1 /*unused*/, alpha + 2*2048, feat + 2*(BB*FEAT_SZ));

    relu_kernel<<<(3*BB*FEAT_SZ + 255)/256, 256>>>(feat, 3*BB*FEAT_SZ);

    conv45_kernel<<<BB, 512>>>(feat + 2*(BB*FEAT_SZ), w2d45, b2d45,
                               feat + 3*(BB*FEAT_SZ), feat + 4*(BB*FEAT_SZ));

    side_kernel<<<dim3(5, BB), 128>>>(x, feat, seg_w, seg_b, so_w, so_b,
                                      sp_wa, sp_ba, sp_wb, sp_bb, sp_sw, sp_sb,
                                      fuse, out);
}